// round 3
// baseline (speedup 1.0000x reference)
#include <cuda_runtime.h>
#include <math.h>

// Problem constants (fixed by the dataset)
#define NN 50000
#define NE 800000
#define FD 50
#define HD 512
#define OD 121
#define NG 20
#define EPSV 1e-5f

// ---------------- scratch (static device arrays; no cudaMalloc allowed) ----
__device__ float g_h1[(size_t)NN * HD];
__device__ float g_h2[(size_t)NN * HD];
__device__ float g_agg[(size_t)NN * HD];
__device__ float g_deg[NN];
__device__ float g_invdeg[NN];
__device__ float g_sz[NG];
__device__ float g_invsz[NG];
__device__ float g_gsum[NG * HD];
__device__ float g_gvar[NG * HD];
__device__ float g_gsc[NG * HD];

// ---------------- utility kernels -----------------------------------------
__global__ void k_zero4(float4* p, int n4) {
    int i = blockIdx.x * blockDim.x + threadIdx.x;
    int stride = gridDim.x * blockDim.x;
    for (; i < n4; i += stride) p[i] = make_float4(0.f, 0.f, 0.f, 0.f);
}

__global__ void k_count(const int* __restrict__ idx, float* __restrict__ cnt, int n) {
    int i = blockIdx.x * blockDim.x + threadIdx.x;
    if (i < n) atomicAdd(&cnt[idx[i]], 1.0f);
}

__global__ void k_recip(const float* __restrict__ a, float* __restrict__ out, int n) {
    int i = blockIdx.x * blockDim.x + threadIdx.x;
    if (i < n) out[i] = 1.0f / fmaxf(a[i], 1.0f);
}

// ---------------- aggregation (scatter-add with vector red) ----------------
__global__ void k_agg512(const float* __restrict__ x, const int* __restrict__ src,
                         const int* __restrict__ dst, float* __restrict__ agg) {
    int gtid = blockIdx.x * blockDim.x + threadIdx.x;
    int e = gtid >> 5;
    if (e >= NE) return;
    int lane = gtid & 31;
    int s = __ldg(&src[e]);
    int d = __ldg(&dst[e]);
    const float* xs = x + (size_t)s * HD;
    float* ad = agg + (size_t)d * HD;
#pragma unroll
    for (int c = lane * 4; c < HD; c += 128) {
        float4 v = *(const float4*)(xs + c);
        asm volatile("red.global.add.v4.f32 [%0], {%1,%2,%3,%4};"
                     :: "l"(ad + c), "f"(v.x), "f"(v.y), "f"(v.z), "f"(v.w)
                     : "memory");
    }
}

__global__ void k_agg50(const float* __restrict__ x, const int* __restrict__ src,
                        const int* __restrict__ dst, float* __restrict__ agg) {
    int gtid = blockIdx.x * blockDim.x + threadIdx.x;
    int e = gtid >> 5;
    if (e >= NE) return;
    int lane = gtid & 31;
    int c = lane * 2;
    if (c >= FD) return;
    int s = __ldg(&src[e]);
    int d = __ldg(&dst[e]);
    float2 v = *(const float2*)(x + (size_t)s * FD + c);
    asm volatile("red.global.add.v2.f32 [%0], {%1,%2};"
                 :: "l"(agg + (size_t)d * FD + c), "f"(v.x), "f"(v.y)
                 : "memory");
}

// ---------------- dual-A SGEMM: C = diag(rs1)*A1 @ W1^T + A2 @ W2^T + bias -
// A* : [Nr, K] row-major, W* : [M, K] row-major (so both read K-contiguous)
#define BM 128
#define BN 128
#define BK 32

__global__ __launch_bounds__(256, 2)
void k_gemm_dual(const float* __restrict__ A1, const float* __restrict__ rs1,
                 const float* __restrict__ W1,
                 const float* __restrict__ A2, const float* __restrict__ W2,
                 const float* __restrict__ bias, float* __restrict__ C,
                 int Nr, int M, int K) {
    __shared__ float As[BK][BM + 4];
    __shared__ float Ws[BK][BN + 4];
    int t = threadIdx.x;
    int rbase = blockIdx.y * BM;
    int cbase = blockIdx.x * BN;
    float acc[8][8];
#pragma unroll
    for (int i = 0; i < 8; i++)
#pragma unroll
        for (int j = 0; j < 8; j++) acc[i][j] = 0.f;

    int lr = t >> 1;         // 0..127 (row within tile for loads)
    int lk = (t & 1) * 16;   // 0 or 16

#pragma unroll 1
    for (int pass = 0; pass < 2; pass++) {
        const float* A = pass ? A2 : A1;
        const float* W = pass ? W2 : W1;
        bool useRs = (pass == 0);
        for (int kb = 0; kb < K; kb += BK) {
            // ---- load A tile (transposed into shared, row-scale applied) ----
            {
                int grow = rbase + lr;
                bool rv = grow < Nr;
                float sc = (useRs && rv) ? rs1[grow] : 1.0f;
                const float* p = A + (size_t)grow * K + kb + lk;
                if (rv && ((K & 3) == 0) && (kb + lk + 16 <= K)) {
#pragma unroll
                    for (int q = 0; q < 4; q++) {
                        float4 v = *(const float4*)(p + q * 4);
                        As[lk + q * 4 + 0][lr] = v.x * sc;
                        As[lk + q * 4 + 1][lr] = v.y * sc;
                        As[lk + q * 4 + 2][lr] = v.z * sc;
                        As[lk + q * 4 + 3][lr] = v.w * sc;
                    }
                } else {
#pragma unroll
                    for (int q = 0; q < 16; q++) {
                        int k = kb + lk + q;
                        As[lk + q][lr] = (rv && k < K) ? A[(size_t)grow * K + k] * sc : 0.f;
                    }
                }
            }
            // ---- load W tile ----
            {
                int grow = cbase + lr;
                bool rv = grow < M;
                const float* p = W + (size_t)grow * K + kb + lk;
                if (rv && ((K & 3) == 0) && (kb + lk + 16 <= K)) {
#pragma unroll
                    for (int q = 0; q < 4; q++) {
                        float4 v = *(const float4*)(p + q * 4);
                        Ws[lk + q * 4 + 0][lr] = v.x;
                        Ws[lk + q * 4 + 1][lr] = v.y;
                        Ws[lk + q * 4 + 2][lr] = v.z;
                        Ws[lk + q * 4 + 3][lr] = v.w;
                    }
                } else {
#pragma unroll
                    for (int q = 0; q < 16; q++) {
                        int k = kb + lk + q;
                        Ws[lk + q][lr] = (rv && k < M * 0 + K) ? ((k < K) ? W[(size_t)grow * K + k] : 0.f) : 0.f;
                    }
                }
            }
            __syncthreads();
            int tr = (t >> 4) * 8, tc = (t & 15) * 8;
#pragma unroll
            for (int kk = 0; kk < BK; kk++) {
                float4 a0 = *(const float4*)&As[kk][tr];
                float4 a1 = *(const float4*)&As[kk][tr + 4];
                float4 b0 = *(const float4*)&Ws[kk][tc];
                float4 b1 = *(const float4*)&Ws[kk][tc + 4];
                float av[8] = {a0.x, a0.y, a0.z, a0.w, a1.x, a1.y, a1.z, a1.w};
                float bv[8] = {b0.x, b0.y, b0.z, b0.w, b1.x, b1.y, b1.z, b1.w};
#pragma unroll
                for (int i = 0; i < 8; i++)
#pragma unroll
                    for (int j = 0; j < 8; j++) acc[i][j] += av[i] * bv[j];
            }
            __syncthreads();
        }
    }
    // ---- epilogue: + bias, store ----
    int tr = (t >> 4) * 8, tc = (t & 15) * 8;
#pragma unroll
    for (int i = 0; i < 8; i++) {
        int row = rbase + tr + i;
        if (row >= Nr) continue;
#pragma unroll
        for (int j = 0; j < 8; j++) {
            int col = cbase + tc + j;
            if (col < M) C[(size_t)row * M + col] = acc[i][j] + bias[col];
        }
    }
}

// ---------------- GraphNorm (batch is sorted, run-length group flush) -------
#define GN_RB 64

__global__ void k_gn_sum(const float* __restrict__ h, const int* __restrict__ batch,
                         float* __restrict__ gsum) {
    int c = threadIdx.x;                       // 512 threads = channels
    int r0 = blockIdx.x * GN_RB;
    int r1 = min(r0 + GN_RB, NN);
    int gcur = batch[r0];
    float acc = 0.f;
    for (int r = r0; r < r1; r++) {
        int g = batch[r];
        if (g != gcur) { atomicAdd(&gsum[gcur * HD + c], acc); acc = 0.f; gcur = g; }
        acc += h[(size_t)r * HD + c];
    }
    atomicAdd(&gsum[gcur * HD + c], acc);
}

__global__ void k_gn_center(float* __restrict__ h, const int* __restrict__ batch,
                            const float* __restrict__ gsum, const float* __restrict__ invsz,
                            const float* __restrict__ alpha, float* __restrict__ gvar) {
    int c = threadIdx.x;
    int r0 = blockIdx.x * GN_RB;
    int r1 = min(r0 + GN_RB, NN);
    float al = alpha[c];
    int gcur = batch[r0];
    float mean = gsum[gcur * HD + c] * invsz[gcur];
    float acc = 0.f;
    for (int r = r0; r < r1; r++) {
        int g = batch[r];
        if (g != gcur) {
            atomicAdd(&gvar[gcur * HD + c], acc); acc = 0.f; gcur = g;
            mean = gsum[g * HD + c] * invsz[g];
        }
        float v = h[(size_t)r * HD + c] - al * mean;
        h[(size_t)r * HD + c] = v;
        acc += v * v;
    }
    atomicAdd(&gvar[gcur * HD + c], acc);
}

__global__ void k_gn_scale(const float* __restrict__ gvar, const float* __restrict__ invsz,
                           const float* __restrict__ w, float* __restrict__ gsc) {
    int i = blockIdx.x * blockDim.x + threadIdx.x;
    if (i < NG * HD) {
        int g = i / HD, c = i - g * HD;
        gsc[i] = rsqrtf(gvar[i] * invsz[g] + EPSV) * w[c];
    }
}

__global__ void k_gn_apply(float* __restrict__ h, const int* __restrict__ batch,
                           const float* __restrict__ gsc, const float* __restrict__ bnb) {
    int i4 = blockIdx.x * blockDim.x + threadIdx.x;   // float4 index
    const int n4 = NN * (HD / 4);
    if (i4 >= n4) return;
    int r = i4 >> 7;                                  // / (HD/4) = 128
    int c4 = (i4 & 127) * 4;
    int g = batch[r];
    float4 v = *((float4*)h + i4);
    float4 s = *(const float4*)&gsc[g * HD + c4];
    float4 b = *(const float4*)&bnb[c4];
    v.x = fmaxf(v.x * s.x + b.x, 0.f);
    v.y = fmaxf(v.y * s.y + b.y, 0.f);
    v.z = fmaxf(v.z * s.z + b.z, 0.f);
    v.w = fmaxf(v.w * s.w + b.w, 0.f);
    *((float4*)h + i4) = v;
}

// ---------------- host-side orchestration ----------------------------------
static float* symaddr(const void* s) {
    void* p = nullptr;
    cudaGetSymbolAddress(&p, s);
    return (float*)p;
}

extern "C" void kernel_launch(void* const* d_in, const int* in_sizes, int n_in,
                              void* d_out, int out_size) {
    const float* x      = (const float*)d_in[0];
    const int*   ei     = (const int*)d_in[1];
    const int*   batch  = (const int*)d_in[2];
    const int*   src    = ei;
    const int*   dst    = ei + NE;

    const float* Wl[5] = {(const float*)d_in[3], (const float*)d_in[6], (const float*)d_in[9],
                          (const float*)d_in[12], (const float*)d_in[15]};
    const float* Wr[5] = {(const float*)d_in[4], (const float*)d_in[7], (const float*)d_in[10],
                          (const float*)d_in[13], (const float*)d_in[16]};
    const float* bb[5] = {(const float*)d_in[5], (const float*)d_in[8], (const float*)d_in[11],
                          (const float*)d_in[14], (const float*)d_in[17]};
    const float* gw[4] = {(const float*)d_in[18], (const float*)d_in[21], (const float*)d_in[24],
                          (const float*)d_in[27]};
    const float* gb[4] = {(const float*)d_in[19], (const float*)d_in[22], (const float*)d_in[25],
                          (const float*)d_in[28]};
    const float* ga[4] = {(const float*)d_in[20], (const float*)d_in[23], (const float*)d_in[26],
                          (const float*)d_in[29]};

    float* h1     = symaddr(g_h1);
    float* h2     = symaddr(g_h2);
    float* agg    = symaddr(g_agg);
    float* deg    = symaddr(g_deg);
    float* invdeg = symaddr(g_invdeg);
    float* szb    = symaddr(g_sz);
    float* invsz  = symaddr(g_invsz);
    float* gsum   = symaddr(g_gsum);
    float* gvar   = symaddr(g_gvar);
    float* gsc    = symaddr(g_gsc);

    auto Z = [&](float* p, size_t n) {
        int n4 = (int)(n / 4);
        int blocks = (n4 + 255) / 256;
        if (blocks > 32768) blocks = 32768;
        k_zero4<<<blocks, 256>>>((float4*)p, n4);
    };

    // ---- degrees & group sizes ----
    Z(deg, NN);
    Z(szb, NG);
    k_count<<<(NE + 255) / 256, 256>>>(dst, deg, NE);
    k_count<<<(NN + 255) / 256, 256>>>(batch, szb, NN);
    k_recip<<<(NN + 255) / 256, 256>>>(deg, invdeg, NN);
    k_recip<<<1, 32>>>(szb, invsz, NG);

    auto gnorm = [&](float* h, const float* w, const float* bias, const float* alpha) {
        Z(gsum, (size_t)NG * HD);
        k_gn_sum<<<(NN + GN_RB - 1) / GN_RB, HD>>>(h, batch, gsum);
        Z(gvar, (size_t)NG * HD);
        k_gn_center<<<(NN + GN_RB - 1) / GN_RB, HD>>>(h, batch, gsum, invsz, alpha, gvar);
        k_gn_scale<<<(NG * HD + 255) / 256, 256>>>(gvar, invsz, w, gsc);
        k_gn_apply<<<(NN * (HD / 4) + 255) / 256, 256>>>(h, batch, gsc, bias);
    };

    const int aggBlocks = (NE * 32) / 256;   // one warp per edge

    // ---- layer 1 (Fin=50 -> 512) ----
    Z(agg, (size_t)NN * FD);
    k_agg50<<<aggBlocks, 256>>>(x, src, dst, agg);
    {
        dim3 grid((HD + BN - 1) / BN, (NN + BM - 1) / BM);
        k_gemm_dual<<<grid, 256>>>(agg, invdeg, Wl[0], x, Wr[0], bb[0], h1, NN, HD, FD);
    }
    gnorm(h1, gw[0], gb[0], ga[0]);

    // ---- layers 2..4 (512 -> 512) ----
    float* cur = h1;
    float* bufs[2] = {h1, h2};
    for (int l = 1; l <= 3; l++) {
        float* nxt = bufs[l & 1];
        Z(agg, (size_t)NN * HD);
        k_agg512<<<aggBlocks, 256>>>(cur, src, dst, agg);
        dim3 grid((HD + BN - 1) / BN, (NN + BM - 1) / BM);
        k_gemm_dual<<<grid, 256>>>(agg, invdeg, Wl[l], cur, Wr[l], bb[l], nxt, NN, HD, HD);
        gnorm(nxt, gw[l], gb[l], ga[l]);
        cur = nxt;
    }

    // ---- layer 5 (512 -> 121) -> d_out ----
    Z(agg, (size_t)NN * HD);
    k_agg512<<<aggBlocks, 256>>>(cur, src, dst, agg);
    {
        dim3 grid((OD + BN - 1) / BN, (NN + BM - 1) / BM);
        k_gemm_dual<<<grid, 256>>>(agg, invdeg, Wl[4], cur, Wr[4], bb[4],
                                   (float*)d_out, NN, OD, HD);
    }
}

// round 5
// speedup vs baseline: 1.5896x; 1.5896x over previous
#include <cuda_runtime.h>
#include <cuda_bf16.h>
#include <cstdint>
#include <math.h>

// Problem constants (fixed by the dataset)
#define NN 50000
#define NE 800000
#define FD 50
#define FDP 64          // padded K for layer 1
#define HD 512
#define OD 121
#define NG 20
#define EPSV 1e-5f

// ---------------- scratch (static device arrays; no cudaMalloc allowed) ----
__device__ float g_h1[(size_t)NN * HD];
__device__ float g_h2[(size_t)NN * HD];
__device__ float g_agg[(size_t)NN * HD];
__device__ float g_deg[NN];
__device__ float g_invdeg[NN];
__device__ float g_sz[NG];
__device__ float g_invsz[NG];
__device__ float g_gsum[NG * HD];
__device__ float g_gvar[NG * HD];
__device__ float g_gsc[NG * HD];
// bf16 hi/lo split buffers
__device__ __nv_bfloat16 g_ah[(size_t)NN * HD];   // agg hi
__device__ __nv_bfloat16 g_al[(size_t)NN * HD];   // agg lo
__device__ __nv_bfloat16 g_xh[(size_t)NN * HD];   // activation hi
__device__ __nv_bfloat16 g_xl[(size_t)NN * HD];   // activation lo
__device__ __nv_bfloat16 g_w1h[HD * HD];
__device__ __nv_bfloat16 g_w1l[HD * HD];
__device__ __nv_bfloat16 g_w2h[HD * HD];
__device__ __nv_bfloat16 g_w2l[HD * HD];

// ---------------- utility kernels -----------------------------------------
__global__ void k_zero4(float4* p, int n4) {
    int i = blockIdx.x * blockDim.x + threadIdx.x;
    int stride = gridDim.x * blockDim.x;
    for (; i < n4; i += stride) p[i] = make_float4(0.f, 0.f, 0.f, 0.f);
}

__global__ void k_count(const int* __restrict__ idx, float* __restrict__ cnt, int n) {
    int i = blockIdx.x * blockDim.x + threadIdx.x;
    if (i < n) atomicAdd(&cnt[idx[i]], 1.0f);
}

__global__ void k_recip(const float* __restrict__ a, float* __restrict__ out, int n) {
    int i = blockIdx.x * blockDim.x + threadIdx.x;
    if (i < n) out[i] = 1.0f / fmaxf(a[i], 1.0f);
}

// split fp32 -> bf16 hi/lo with optional row scale and K padding
__global__ void k_split(const float* __restrict__ in, const float* __restrict__ rs,
                        __nv_bfloat16* __restrict__ hi, __nv_bfloat16* __restrict__ lo,
                        int rows, int Kin, int Kpad) {
    int idx = blockIdx.x * blockDim.x + threadIdx.x;
    int total = rows * Kpad;
    int stride = gridDim.x * blockDim.x;
    for (; idx < total; idx += stride) {
        int r = idx / Kpad;
        int c = idx - r * Kpad;
        float v = 0.f;
        if (c < Kin) {
            v = in[(size_t)r * Kin + c];
            if (rs) v *= rs[r];
        }
        __nv_bfloat16 h = __float2bfloat16_rn(v);
        hi[idx] = h;
        lo[idx] = __float2bfloat16_rn(v - __bfloat162float(h));
    }
}

// ---------------- aggregation (scatter-add with vector red) ----------------
__global__ void k_agg512(const float* __restrict__ x, const int* __restrict__ src,
                         const int* __restrict__ dst, float* __restrict__ agg) {
    int gtid = blockIdx.x * blockDim.x + threadIdx.x;
    int e = gtid >> 5;
    if (e >= NE) return;
    int lane = gtid & 31;
    int s = __ldg(&src[e]);
    int d = __ldg(&dst[e]);
    const float* xs = x + (size_t)s * HD;
    float* ad = agg + (size_t)d * HD;
#pragma unroll
    for (int c = lane * 4; c < HD; c += 128) {
        float4 v = *(const float4*)(xs + c);
        asm volatile("red.global.add.v4.f32 [%0], {%1,%2,%3,%4};"
                     :: "l"(ad + c), "f"(v.x), "f"(v.y), "f"(v.z), "f"(v.w)
                     : "memory");
    }
}

__global__ void k_agg50(const float* __restrict__ x, const int* __restrict__ src,
                        const int* __restrict__ dst, float* __restrict__ agg) {
    int gtid = blockIdx.x * blockDim.x + threadIdx.x;
    int e = gtid >> 5;
    if (e >= NE) return;
    int lane = gtid & 31;
    int c = lane * 2;
    if (c >= FD) return;
    int s = __ldg(&src[e]);
    int d = __ldg(&dst[e]);
    float2 v = *(const float2*)(x + (size_t)s * FD + c);
    asm volatile("red.global.add.v2.f32 [%0], {%1,%2};"
                 :: "l"(agg + (size_t)d * FD + c), "f"(v.x), "f"(v.y)
                 : "memory");
}

// ---------------- tensor-core dual GEMM ------------------------------------
// C = Ah1@Wh1^T + Al1@Wh1^T + Ah1@Wl1^T + Ah2@Wh2^T + Al2@Wh2^T + Ah2@Wl2^T + bias
// All bf16 matrices row-major [rows][K] (K padded to multiple of 32).
#define GBM 128
#define GBN 128
#define GBK 32
#define ASTRIDE 40   // smem row stride in elements (80B: conflict-free ldmatrix)

#define LDM_X4(r0_, r1_, r2_, r3_, addr_)                                        \
    asm volatile("ldmatrix.sync.aligned.m8n8.x4.shared.b16 {%0,%1,%2,%3}, [%4];" \
                 : "=r"(r0_), "=r"(r1_), "=r"(r2_), "=r"(r3_) : "r"(addr_))

#define MMA16816(c_, a_, b_)                                                   \
    asm volatile("mma.sync.aligned.m16n8k16.row.col.f32.bf16.bf16.f32 "        \
                 "{%0,%1,%2,%3}, {%4,%5,%6,%7}, {%8,%9}, {%0,%1,%2,%3};"       \
                 : "+f"(c_[0]), "+f"(c_[1]), "+f"(c_[2]), "+f"(c_[3])          \
                 : "r"(a_[0]), "r"(a_[1]), "r"(a_[2]), "r"(a_[3]),             \
                   "r"(b_[0]), "r"(b_[1]))

__device__ __forceinline__ void cp16(uint32_t dst, const void* src, int okbytes) {
    asm volatile("cp.async.cg.shared.global [%0], [%1], 16, %2;"
                 :: "r"(dst), "l"(src), "r"(okbytes));
}

__device__ __forceinline__ void tile_load(int t, const __nv_bfloat16* A,
                                          const __nv_bfloat16* W, int rbase, int cbase,
                                          int kb, int K, int Nr, int M,
                                          uint32_t sA_u32, uint32_t sW_u32) {
#pragma unroll
    for (int p = 0; p < 2; p++) {
        int c = t + p * 256;
        int row = c >> 2;
        int seg = c & 3;
        uint32_t soff = (uint32_t)(row * ASTRIDE + seg * 8) * 2;
        // A side
        int grow = rbase + row;
        int okA = (grow < Nr) ? 16 : 0;
        int ga = (grow < Nr) ? grow : 0;
        cp16(sA_u32 + soff, A + (size_t)ga * K + kb + seg * 8, okA);
        // W side
        int wrow = cbase + row;
        int okW = (wrow < M) ? 16 : 0;
        int gw = (wrow < M) ? wrow : 0;
        cp16(sW_u32 + soff, W + (size_t)gw * K + kb + seg * 8, okW);
    }
}

__global__ __launch_bounds__(256, 2)
void k_gemm_tc(const __nv_bfloat16* __restrict__ Ah1, const __nv_bfloat16* __restrict__ Al1,
               const __nv_bfloat16* __restrict__ Wh1, const __nv_bfloat16* __restrict__ Wl1,
               const __nv_bfloat16* __restrict__ Ah2, const __nv_bfloat16* __restrict__ Al2,
               const __nv_bfloat16* __restrict__ Wh2, const __nv_bfloat16* __restrict__ Wl2,
               const float* __restrict__ bias, float* __restrict__ C,
               int Nr, int M, int K) {
    __shared__ __align__(16) __nv_bfloat16 sA[2][GBM * ASTRIDE];
    __shared__ __align__(16) __nv_bfloat16 sW[2][GBM * ASTRIDE];

    int t = threadIdx.x;
    int lane = t & 31;
    int wid = t >> 5;
    int wm = (wid >> 2) * 64;    // warp row offset in tile
    int wn = (wid & 3) * 32;     // warp col offset in tile
    int rbase = blockIdx.y * GBM;
    int cbase = blockIdx.x * GBN;

    float acc[4][4][4];
#pragma unroll
    for (int i = 0; i < 4; i++)
#pragma unroll
        for (int j = 0; j < 4; j++)
#pragma unroll
            for (int q = 0; q < 4; q++) acc[i][j][q] = 0.f;

    uint32_t sAu[2] = {(uint32_t)__cvta_generic_to_shared(&sA[0][0]),
                       (uint32_t)__cvta_generic_to_shared(&sA[1][0])};
    uint32_t sWu[2] = {(uint32_t)__cvta_generic_to_shared(&sW[0][0]),
                       (uint32_t)__cvta_generic_to_shared(&sW[1][0])};

    const int itersPer = K / GBK;
    const int total = 6 * itersPer;

    auto pick = [&](int it, const __nv_bfloat16*& Ap, const __nv_bfloat16*& Wp, int& kb) {
        int s = it / itersPer;
        kb = (it - s * itersPer) * GBK;
        switch (s) {
            case 0: Ap = Ah1; Wp = Wh1; break;
            case 1: Ap = Al1; Wp = Wh1; break;
            case 2: Ap = Ah1; Wp = Wl1; break;
            case 3: Ap = Ah2; Wp = Wh2; break;
            case 4: Ap = Al2; Wp = Wh2; break;
            default: Ap = Ah2; Wp = Wl2; break;
        }
    };

    // ldmatrix per-lane offsets
    int g = lane >> 3;
    int rA = (lane & 7) + ((g & 1) << 3);
    int kA = (g >> 1) << 3;
    int rB = (lane & 7) + ((g >> 1) << 3);
    int kB = (g & 1) << 3;

    // prologue
    {
        const __nv_bfloat16 *Ap, *Wp; int kb;
        pick(0, Ap, Wp, kb);
        tile_load(t, Ap, Wp, rbase, cbase, kb, K, Nr, M, sAu[0], sWu[0]);
        asm volatile("cp.async.commit_group;");
    }

    int buf = 0;
    for (int it = 0; it < total; it++) {
        if (it + 1 < total) {
            const __nv_bfloat16 *Ap, *Wp; int kb;
            pick(it + 1, Ap, Wp, kb);
            tile_load(t, Ap, Wp, rbase, cbase, kb, K, Nr, M, sAu[buf ^ 1], sWu[buf ^ 1]);
            asm volatile("cp.async.commit_group;");
            asm volatile("cp.async.wait_group 1;");
        } else {
            asm volatile("cp.async.wait_group 0;");
        }
        __syncthreads();

        uint32_t baseA = sAu[buf];
        uint32_t baseW = sWu[buf];
#pragma unroll
        for (int s = 0; s < 2; s++) {
            uint32_t afrag[4][4];
#pragma unroll
            for (int mt = 0; mt < 4; mt++) {
                uint32_t addr = baseA + (uint32_t)((wm + mt * 16 + rA) * ASTRIDE + s * 16 + kA) * 2;
                LDM_X4(afrag[mt][0], afrag[mt][1], afrag[mt][2], afrag[mt][3], addr);
            }
            uint32_t bfrag[4][2];
#pragma unroll
            for (int np = 0; np < 2; np++) {
                uint32_t addr = baseW + (uint32_t)((wn + np * 16 + rB) * ASTRIDE + s * 16 + kB) * 2;
                uint32_t q0, q1, q2, q3;
                LDM_X4(q0, q1, q2, q3, addr);
                bfrag[np * 2][0] = q0; bfrag[np * 2][1] = q1;
                bfrag[np * 2 + 1][0] = q2; bfrag[np * 2 + 1][1] = q3;
            }
#pragma unroll
            for (int mt = 0; mt < 4; mt++)
#pragma unroll
                for (int nt = 0; nt < 4; nt++) MMA16816(acc[mt][nt], afrag[mt], bfrag[nt]);
        }
        __syncthreads();
        buf ^= 1;
    }

    // epilogue: bias + store
#pragma unroll
    for (int mt = 0; mt < 4; mt++) {
        int row0 = rbase + wm + mt * 16 + (lane >> 2);
        int row1 = row0 + 8;
#pragma unroll
        for (int nt = 0; nt < 4; nt++) {
            int col0 = cbase + wn + nt * 8 + (lane & 3) * 2;
            if (col0 < M) {
                float b0 = bias[col0];
                if (row0 < Nr) C[(size_t)row0 * M + col0] = acc[mt][nt][0] + b0;
                if (row1 < Nr) C[(size_t)row1 * M + col0] = acc[mt][nt][2] + b0;
            }
            if (col0 + 1 < M) {
                float b1 = bias[col0 + 1];
                if (row0 < Nr) C[(size_t)row0 * M + col0 + 1] = acc[mt][nt][1] + b1;
                if (row1 < Nr) C[(size_t)row1 * M + col0 + 1] = acc[mt][nt][3] + b1;
            }
        }
    }
}

// ---------------- GraphNorm (batch is sorted, run-length group flush) -------
#define GN_RB 64

__global__ void k_gn_sum(const float* __restrict__ h, const int* __restrict__ batch,
                         float* __restrict__ gsum) {
    int c = threadIdx.x;
    int r0 = blockIdx.x * GN_RB;
    int r1 = min(r0 + GN_RB, NN);
    int gcur = batch[r0];
    float acc = 0.f;
    for (int r = r0; r < r1; r++) {
        int g = batch[r];
        if (g != gcur) { atomicAdd(&gsum[gcur * HD + c], acc); acc = 0.f; gcur = g; }
        acc += h[(size_t)r * HD + c];
    }
    atomicAdd(&gsum[gcur * HD + c], acc);
}

__global__ void k_gn_center(float* __restrict__ h, const int* __restrict__ batch,
                            const float* __restrict__ gsum, const float* __restrict__ invsz,
                            const float* __restrict__ alpha, float* __restrict__ gvar) {
    int c = threadIdx.x;
    int r0 = blockIdx.x * GN_RB;
    int r1 = min(r0 + GN_RB, NN);
    float al = alpha[c];
    int gcur = batch[r0];
    float mean = gsum[gcur * HD + c] * invsz[gcur];
    float acc = 0.f;
    for (int r = r0; r < r1; r++) {
        int g = batch[r];
        if (g != gcur) {
            atomicAdd(&gvar[gcur * HD + c], acc); acc = 0.f; gcur = g;
            mean = gsum[g * HD + c] * invsz[g];
        }
        float v = h[(size_t)r * HD + c] - al * mean;
        h[(size_t)r * HD + c] = v;
        acc += v * v;
    }
    atomicAdd(&gvar[gcur * HD + c], acc);
}

__global__ void k_gn_scale(const float* __restrict__ gvar, const float* __restrict__ invsz,
                           const float* __restrict__ w, float* __restrict__ gsc) {
    int i = blockIdx.x * blockDim.x + threadIdx.x;
    if (i < NG * HD) {
        int g = i / HD, c = i - g * HD;
        gsc[i] = rsqrtf(gvar[i] * invsz[g] + EPSV) * w[c];
    }
}

// apply scale+bias+relu, write fp32 back AND the bf16 hi/lo split
__global__ void k_gn_apply(float* __restrict__ h, const int* __restrict__ batch,
                           const float* __restrict__ gsc, const float* __restrict__ bnb,
                           __nv_bfloat16* __restrict__ xh, __nv_bfloat16* __restrict__ xl) {
    int i4 = blockIdx.x * blockDim.x + threadIdx.x;
    const int n4 = NN * (HD / 4);
    if (i4 >= n4) return;
    int r = i4 >> 7;
    int c4 = (i4 & 127) * 4;
    int g = batch[r];
    float4 v = *((float4*)h + i4);
    float4 s = *(const float4*)&gsc[g * HD + c4];
    float4 b = *(const float4*)&bnb[c4];
    v.x = fmaxf(v.x * s.x + b.x, 0.f);
    v.y = fmaxf(v.y * s.y + b.y, 0.f);
    v.z = fmaxf(v.z * s.z + b.z, 0.f);
    v.w = fmaxf(v.w * s.w + b.w, 0.f);
    *((float4*)h + i4) = v;

    __nv_bfloat162 h01, h23, l01, l23;
    h01.x = __float2bfloat16_rn(v.x); h01.y = __float2bfloat16_rn(v.y);
    h23.x = __float2bfloat16_rn(v.z); h23.y = __float2bfloat16_rn(v.w);
    l01.x = __float2bfloat16_rn(v.x - __bfloat162float(h01.x));
    l01.y = __float2bfloat16_rn(v.y - __bfloat162float(h01.y));
    l23.x = __float2bfloat16_rn(v.z - __bfloat162float(h23.x));
    l23.y = __float2bfloat16_rn(v.w - __bfloat162float(h23.y));
    *(__nv_bfloat162*)(xh + (size_t)i4 * 4) = h01;
    *(__nv_bfloat162*)(xh + (size_t)i4 * 4 + 2) = h23;
    *(__nv_bfloat162*)(xl + (size_t)i4 * 4) = l01;
    *(__nv_bfloat162*)(xl + (size_t)i4 * 4 + 2) = l23;
}

// ---------------- host-side orchestration ----------------------------------
static float* symaddrf(const void* s) {
    void* p = nullptr;
    cudaGetSymbolAddress(&p, s);
    return (float*)p;
}
static __nv_bfloat16* symaddrb(const void* s) {
    void* p = nullptr;
    cudaGetSymbolAddress(&p, s);
    return (__nv_bfloat16*)p;
}

extern "C" void kernel_launch(void* const* d_in, const int* in_sizes, int n_in,
                              void* d_out, int out_size) {
    const float* x      = (const float*)d_in[0];
    const int*   ei     = (const int*)d_in[1];
    const int*   batch  = (const int*)d_in[2];
    const int*   src    = ei;
    const int*   dst    = ei + NE;

    const float* Wl[5] = {(const float*)d_in[3], (const float*)d_in[6], (const float*)d_in[9],
                          (const float*)d_in[12], (const float*)d_in[15]};
    const float* Wr[5] = {(const float*)d_in[4], (const float*)d_in[7], (const float*)d_in[10],
                          (const float*)d_in[13], (const float*)d_in[16]};
    const float* bb[5] = {(const float*)d_in[5], (const float*)d_in[8], (const float*)d_in[11],
                          (const float*)d_in[14], (const float*)d_in[17]};
    const float* gw[4] = {(const float*)d_in[18], (const float*)d_in[21], (const float*)d_in[24],
                          (const float*)d_in[27]};
    const float* gb[4] = {(const float*)d_in[19], (const float*)d_in[22], (const float*)d_in[25],
                          (const float*)d_in[28]};
    const float* ga[4] = {(const float*)d_in[20], (const float*)d_in[23], (const float*)d_in[26],
                          (const float*)d_in[29]};

    float* h1     = symaddrf(g_h1);
    float* h2     = symaddrf(g_h2);
    float* agg    = symaddrf(g_agg);
    float* deg    = symaddrf(g_deg);
    float* invdeg = symaddrf(g_invdeg);
    float* szb    = symaddrf(g_sz);
    float* invsz  = symaddrf(g_invsz);
    float* gsum   = symaddrf(g_gsum);
    float* gvar   = symaddrf(g_gvar);
    float* gsc    = symaddrf(g_gsc);
    __nv_bfloat16* ah  = symaddrb(g_ah);
    __nv_bfloat16* al  = symaddrb(g_al);
    __nv_bfloat16* xh  = symaddrb(g_xh);
    __nv_bfloat16* xl  = symaddrb(g_xl);
    __nv_bfloat16* w1h = symaddrb(g_w1h);
    __nv_bfloat16* w1l = symaddrb(g_w1l);
    __nv_bfloat16* w2h = symaddrb(g_w2h);
    __nv_bfloat16* w2l = symaddrb(g_w2l);

    auto Z = [&](float* p, size_t n) {
        int n4 = (int)(n / 4);
        int blocks = (n4 + 255) / 256;
        if (blocks > 32768) blocks = 32768;
        k_zero4<<<blocks, 256>>>((float4*)p, n4);
    };
    auto SPLIT = [&](const float* in, const float* rs, __nv_bfloat16* hi, __nv_bfloat16* lo,
                     int rows, int Kin, int Kpad) {
        int total = rows * Kpad;
        int blocks = (total + 255) / 256;
        if (blocks > 65535) blocks = 65535;
        k_split<<<blocks, 256>>>(in, rs, hi, lo, rows, Kin, Kpad);
    };

    // ---- degrees & group sizes ----
    Z(deg, NN);
    Z(szb, NG);
    k_count<<<(NE + 255) / 256, 256>>>(dst, deg, NE);
    k_count<<<(NN + 255) / 256, 256>>>(batch, szb, NN);
    k_recip<<<(NN + 255) / 256, 256>>>(deg, invdeg, NN);
    k_recip<<<1, 32>>>(szb, invsz, NG);

    auto gnorm = [&](float* h, const float* w, const float* bias, const float* alpha) {
        Z(gsum, (size_t)NG * HD);
        k_gn_sum<<<(NN + GN_RB - 1) / GN_RB, HD>>>(h, batch, gsum);
        Z(gvar, (size_t)NG * HD);
        k_gn_center<<<(NN + GN_RB - 1) / GN_RB, HD>>>(h, batch, gsum, invsz, alpha, gvar);
        k_gn_scale<<<(NG * HD + 255) / 256, 256>>>(gvar, invsz, w, gsc);
        k_gn_apply<<<(NN * (HD / 4) + 255) / 256, 256>>>(h, batch, gsc, bias, xh, xl);
    };

    const int aggBlocks = (NE * 32) / 256;   // one warp per edge

    // ---- layer 1 (Fin=50 -> 512) ----
    Z(agg, (size_t)NN * FD);
    k_agg50<<<aggBlocks, 256>>>(x, src, dst, agg);
    SPLIT(agg, invdeg, ah, al, NN, FD, FDP);
    SPLIT(x, nullptr, xh, xl, NN, FD, FDP);
    SPLIT(Wl[0], nullptr, w1h, w1l, HD, FD, FDP);
    SPLIT(Wr[0], nullptr, w2h, w2l, HD, FD, FDP);
    {
        dim3 grid(HD / GBN, (NN + GBM - 1) / GBM);
        k_gemm_tc<<<grid, 256>>>(ah, al, w1h, w1l, xh, xl, w2h, w2l, bb[0], h1,
                                 NN, HD, FDP);
    }
    gnorm(h1, gw[0], gb[0], ga[0]);   // also refreshes xh/xl = split(h1)

    // ---- layers 2..4 (512 -> 512) ----
    float* cur = h1;
    float* bufs[2] = {h1, h2};
    for (int l = 1; l <= 3; l++) {
        float* nxt = bufs[l & 1];
        Z(agg, (size_t)NN * HD);
        k_agg512<<<aggBlocks, 256>>>(cur, src, dst, agg);
        SPLIT(agg, invdeg, ah, al, NN, HD, HD);
        SPLIT(Wl[l], nullptr, w1h, w1l, HD, HD, HD);
        SPLIT(Wr[l], nullptr, w2h, w2l, HD, HD, HD);
        dim3 grid(HD / GBN, (NN + GBM - 1) / GBM);
        k_gemm_tc<<<grid, 256>>>(ah, al, w1h, w1l, xh, xl, w2h, w2l, bb[l], nxt,
                                 NN, HD, HD);
        gnorm(nxt, gw[l], gb[l], ga[l]);
        cur = nxt;
    }

    // ---- layer 5 (512 -> 121) -> d_out ----
    Z(agg, (size_t)NN * HD);
    k_agg512<<<aggBlocks, 256>>>(cur, src, dst, agg);
    SPLIT(agg, invdeg, ah, al, NN, HD, HD);
    SPLIT(Wl[4], nullptr, w1h, w1l, OD, HD, HD);
    SPLIT(Wr[4], nullptr, w2h, w2l, OD, HD, HD);
    {
        dim3 grid((OD + GBN - 1) / GBN, (NN + GBM - 1) / GBM);
        k_gemm_tc<<<grid, 256>>>(ah, al, w1h, w1l, xh, xl, w2h, w2l, bb[4],
                                 (float*)d_out, NN, OD, HD);
    }
}

// round 6
// speedup vs baseline: 2.5791x; 1.6225x over previous
#include <cuda_runtime.h>
#include <cuda_bf16.h>
#include <cstdint>
#include <math.h>

#define NN 50000
#define NE 800000
#define FD 50
#define FDP 64
#define HD 512
#define OD 121
#define NG 20
#define EPSV 1e-5f

// ---------------- scratch ---------------------------------------------------
__device__ float g_h1[(size_t)NN * HD];
__device__ int   g_degi[NN];
__device__ int   g_rowptr[NN + 1];
__device__ int   g_cursor[NN];
__device__ int   g_csr[NE];
__device__ float g_invsz[NG];
__device__ float g_gsum[NG * HD];
__device__ float g_gsq[NG * HD];
__device__ float g_gS[NG * HD];
__device__ float g_gT[NG * HD];
__device__ __nv_bfloat16 g_ah[(size_t)NN * HD];
__device__ __nv_bfloat16 g_al[(size_t)NN * HD];
__device__ __nv_bfloat16 g_xh[(size_t)NN * HD];
__device__ __nv_bfloat16 g_xl[(size_t)NN * HD];
__device__ __nv_bfloat16 g_w1h[HD * HD];
__device__ __nv_bfloat16 g_w1l[HD * HD];
__device__ __nv_bfloat16 g_w2h[HD * HD];
__device__ __nv_bfloat16 g_w2l[HD * HD];

// ---------------- utility ---------------------------------------------------
__global__ void k_zero4(float4* p, int n4) {
    int i = blockIdx.x * blockDim.x + threadIdx.x;
    int stride = gridDim.x * blockDim.x;
    for (; i < n4; i += stride) p[i] = make_float4(0.f, 0.f, 0.f, 0.f);
}

__global__ void k_count_i(const int* __restrict__ idx, int* __restrict__ cnt, int n) {
    int i = blockIdx.x * blockDim.x + threadIdx.x;
    if (i < n) atomicAdd(&cnt[idx[i]], 1);
}

// group sizes via binary search (batch is sorted)
__global__ void k_group_sizes(const int* __restrict__ batch, float* __restrict__ invsz) {
    int g = threadIdx.x;
    if (g >= NG) return;
    // lower bound of g
    int lo = 0, hi = NN;
    while (lo < hi) { int m = (lo + hi) >> 1; if (batch[m] < g) lo = m + 1; else hi = m; }
    int lb = lo;
    lo = 0; hi = NN;
    while (lo < hi) { int m = (lo + hi) >> 1; if (batch[m] < g + 1) lo = m + 1; else hi = m; }
    int sz = lo - lb;
    invsz[g] = 1.0f / fmaxf((float)sz, 1.0f);
}

// single-block exclusive scan over degrees -> rowptr
__global__ void k_scan(const int* __restrict__ deg, int* __restrict__ rowptr) {
    __shared__ int sh[1024];
    int tid = threadIdx.x;
    int off = 0;
    for (int base = 0; base < NN; base += 1024) {
        int i = base + tid;
        int v = (i < NN) ? deg[i] : 0;
        sh[tid] = v;
        __syncthreads();
#pragma unroll
        for (int d = 1; d < 1024; d <<= 1) {
            int t = (tid >= d) ? sh[tid - d] : 0;
            __syncthreads();
            sh[tid] += t;
            __syncthreads();
        }
        if (i < NN) rowptr[i] = off + sh[tid] - v;
        off += sh[1023];
        __syncthreads();
    }
    if (tid == 0) rowptr[NN] = off;
}

__global__ void k_scatter(const int* __restrict__ src, const int* __restrict__ dst,
                          const int* __restrict__ rowptr, int* __restrict__ cursor,
                          int* __restrict__ csr) {
    int e = blockIdx.x * blockDim.x + threadIdx.x;
    if (e >= NE) return;
    int d = dst[e];
    int p = atomicAdd(&cursor[d], 1);
    csr[rowptr[d] + p] = src[e];
}

// split fp32 -> bf16 hi/lo with K padding (x and weights)
__global__ void k_split(const float* __restrict__ in,
                        __nv_bfloat16* __restrict__ hi, __nv_bfloat16* __restrict__ lo,
                        int rows, int Kin, int Kpad) {
    int idx = blockIdx.x * blockDim.x + threadIdx.x;
    int total = rows * Kpad;
    int stride = gridDim.x * blockDim.x;
    for (; idx < total; idx += stride) {
        int r = idx / Kpad;
        int c = idx - r * Kpad;
        float v = (c < Kin) ? in[(size_t)r * Kin + c] : 0.f;
        __nv_bfloat16 h = __float2bfloat16_rn(v);
        hi[idx] = h;
        lo[idx] = __float2bfloat16_rn(v - __bfloat162float(h));
    }
}

// ---------------- CSR aggregation ------------------------------------------
__device__ __forceinline__ void addb4(float4& a, uint2 u) {
    __nv_bfloat162 p0 = *reinterpret_cast<__nv_bfloat162*>(&u.x);
    __nv_bfloat162 p1 = *reinterpret_cast<__nv_bfloat162*>(&u.y);
    a.x += __low2float(p0); a.y += __high2float(p0);
    a.z += __low2float(p1); a.w += __high2float(p1);
}

// 512-ch: one block (128 thr) per node; reads bf16 hi/lo activations,
// writes inv_deg-scaled bf16 hi/lo agg. No atomics, no zero-init.
__global__ __launch_bounds__(128)
void k_aggcsr512(const __nv_bfloat16* __restrict__ xh, const __nv_bfloat16* __restrict__ xl,
                 const int* __restrict__ rowptr, const int* __restrict__ csr,
                 __nv_bfloat16* __restrict__ ah, __nv_bfloat16* __restrict__ al) {
    int node = blockIdx.x;
    int c = threadIdx.x * 4;
    int start = __ldg(&rowptr[node]);
    int end = __ldg(&rowptr[node + 1]);
    float4 acc = make_float4(0.f, 0.f, 0.f, 0.f);
    int j = start;
    for (; j + 1 < end; j += 2) {
        int s0 = __ldg(&csr[j]);
        int s1 = __ldg(&csr[j + 1]);
        uint2 h0 = *(const uint2*)(xh + (size_t)s0 * HD + c);
        uint2 l0 = *(const uint2*)(xl + (size_t)s0 * HD + c);
        uint2 h1 = *(const uint2*)(xh + (size_t)s1 * HD + c);
        uint2 l1 = *(const uint2*)(xl + (size_t)s1 * HD + c);
        addb4(acc, h0); addb4(acc, l0);
        addb4(acc, h1); addb4(acc, l1);
    }
    if (j < end) {
        int s0 = __ldg(&csr[j]);
        uint2 h0 = *(const uint2*)(xh + (size_t)s0 * HD + c);
        uint2 l0 = *(const uint2*)(xl + (size_t)s0 * HD + c);
        addb4(acc, h0); addb4(acc, l0);
    }
    float inv = 1.0f / fmaxf((float)(end - start), 1.0f);
    acc.x *= inv; acc.y *= inv; acc.z *= inv; acc.w *= inv;
    __nv_bfloat162 h01, h23, l01, l23;
    h01.x = __float2bfloat16_rn(acc.x); h01.y = __float2bfloat16_rn(acc.y);
    h23.x = __float2bfloat16_rn(acc.z); h23.y = __float2bfloat16_rn(acc.w);
    l01.x = __float2bfloat16_rn(acc.x - __bfloat162float(h01.x));
    l01.y = __float2bfloat16_rn(acc.y - __bfloat162float(h01.y));
    l23.x = __float2bfloat16_rn(acc.z - __bfloat162float(h23.x));
    l23.y = __float2bfloat16_rn(acc.w - __bfloat162float(h23.y));
    __nv_bfloat162* ph = (__nv_bfloat162*)(ah + (size_t)node * HD + c);
    __nv_bfloat162* pl = (__nv_bfloat162*)(al + (size_t)node * HD + c);
    ph[0] = h01; ph[1] = h23;
    pl[0] = l01; pl[1] = l23;
}

// layer-1 aggregation from fp32 x (FD=50 -> padded FDP=64 output)
__global__ __launch_bounds__(64)
void k_aggcsr50(const float* __restrict__ x,
                const int* __restrict__ rowptr, const int* __restrict__ csr,
                __nv_bfloat16* __restrict__ ah, __nv_bfloat16* __restrict__ al) {
    int node = blockIdx.x;
    int c = threadIdx.x;
    int start = __ldg(&rowptr[node]);
    int end = __ldg(&rowptr[node + 1]);
    float acc = 0.f;
    if (c < FD) {
        for (int j = start; j < end; j++) {
            int s = __ldg(&csr[j]);
            acc += __ldg(&x[(size_t)s * FD + c]);
        }
    }
    float inv = 1.0f / fmaxf((float)(end - start), 1.0f);
    float v = acc * inv;
    __nv_bfloat16 h = __float2bfloat16_rn(v);
    ah[(size_t)node * FDP + c] = h;
    al[(size_t)node * FDP + c] = __float2bfloat16_rn(v - __bfloat162float(h));
}

// ---------------- tensor-core dual GEMM ------------------------------------
#define GBM 128
#define GBN 128
#define GBK 32
#define ASTRIDE 40

#define LDM_X4(r0_, r1_, r2_, r3_, addr_)                                        \
    asm volatile("ldmatrix.sync.aligned.m8n8.x4.shared.b16 {%0,%1,%2,%3}, [%4];" \
                 : "=r"(r0_), "=r"(r1_), "=r"(r2_), "=r"(r3_) : "r"(addr_))

#define MMA16816(c_, a_, b_)                                                   \
    asm volatile("mma.sync.aligned.m16n8k16.row.col.f32.bf16.bf16.f32 "        \
                 "{%0,%1,%2,%3}, {%4,%5,%6,%7}, {%8,%9}, {%0,%1,%2,%3};"       \
                 : "+f"(c_[0]), "+f"(c_[1]), "+f"(c_[2]), "+f"(c_[3])          \
                 : "r"(a_[0]), "r"(a_[1]), "r"(a_[2]), "r"(a_[3]),             \
                   "r"(b_[0]), "r"(b_[1]))

__device__ __forceinline__ void cp16(uint32_t dst, const void* src, int okbytes) {
    asm volatile("cp.async.cg.shared.global [%0], [%1], 16, %2;"
                 :: "r"(dst), "l"(src), "r"(okbytes));
}

__device__ __forceinline__ void tile_load(int t, const __nv_bfloat16* A,
                                          const __nv_bfloat16* W, int rbase, int cbase,
                                          int kb, int K, int Nr, int M,
                                          uint32_t sA_u32, uint32_t sW_u32) {
#pragma unroll
    for (int p = 0; p < 2; p++) {
        int c = t + p * 256;
        int row = c >> 2;
        int seg = c & 3;
        uint32_t soff = (uint32_t)(row * ASTRIDE + seg * 8) * 2;
        int grow = rbase + row;
        int okA = (grow < Nr) ? 16 : 0;
        int ga = (grow < Nr) ? grow : 0;
        cp16(sA_u32 + soff, A + (size_t)ga * K + kb + seg * 8, okA);
        int wrow = cbase + row;
        int okW = (wrow < M) ? 16 : 0;
        int gw = (wrow < M) ? wrow : 0;
        cp16(sW_u32 + soff, W + (size_t)gw * K + kb + seg * 8, okW);
    }
}

__global__ __launch_bounds__(256, 2)
void k_gemm_tc(const __nv_bfloat16* __restrict__ Ah1, const __nv_bfloat16* __restrict__ Al1,
               const __nv_bfloat16* __restrict__ Wh1, const __nv_bfloat16* __restrict__ Wl1,
               const __nv_bfloat16* __restrict__ Ah2, const __nv_bfloat16* __restrict__ Al2,
               const __nv_bfloat16* __restrict__ Wh2, const __nv_bfloat16* __restrict__ Wl2,
               const float* __restrict__ bias, float* __restrict__ C,
               int Nr, int M, int K) {
    __shared__ __align__(16) __nv_bfloat16 sA[2][GBM * ASTRIDE];
    __shared__ __align__(16) __nv_bfloat16 sW[2][GBM * ASTRIDE];

    int t = threadIdx.x;
    int lane = t & 31;
    int wid = t >> 5;
    int wm = (wid >> 2) * 64;
    int wn = (wid & 3) * 32;
    int rbase = blockIdx.y * GBM;
    int cbase = blockIdx.x * GBN;

    float acc[4][4][4];
#pragma unroll
    for (int i = 0; i < 4; i++)
#pragma unroll
        for (int j = 0; j < 4; j++)
#pragma unroll
            for (int q = 0; q < 4; q++) acc[i][j][q] = 0.f;

    uint32_t sAu[2] = {(uint32_t)__cvta_generic_to_shared(&sA[0][0]),
                       (uint32_t)__cvta_generic_to_shared(&sA[1][0])};
    uint32_t sWu[2] = {(uint32_t)__cvta_generic_to_shared(&sW[0][0]),
                       (uint32_t)__cvta_generic_to_shared(&sW[1][0])};

    const int itersPer = K / GBK;
    const int total = 6 * itersPer;

    auto pick = [&](int it, const __nv_bfloat16*& Ap, const __nv_bfloat16*& Wp, int& kb) {
        int s = it / itersPer;
        kb = (it - s * itersPer) * GBK;
        switch (s) {
            case 0: Ap = Ah1; Wp = Wh1; break;
            case 1: Ap = Al1; Wp = Wh1; break;
            case 2: Ap = Ah1; Wp = Wl1; break;
            case 3: Ap = Ah2; Wp = Wh2; break;
            case 4: Ap = Al2; Wp = Wh2; break;
            default: Ap = Ah2; Wp = Wl2; break;
        }
    };

    int g = lane >> 3;
    int rA = (lane & 7) + ((g & 1) << 3);
    int kA = (g >> 1) << 3;
    int rB = (lane & 7) + ((g >> 1) << 3);
    int kB = (g & 1) << 3;

    {
        const __nv_bfloat16 *Ap, *Wp; int kb;
        pick(0, Ap, Wp, kb);
        tile_load(t, Ap, Wp, rbase, cbase, kb, K, Nr, M, sAu[0], sWu[0]);
        asm volatile("cp.async.commit_group;");
    }

    int buf = 0;
    for (int it = 0; it < total; it++) {
        if (it + 1 < total) {
            const __nv_bfloat16 *Ap, *Wp; int kb;
            pick(it + 1, Ap, Wp, kb);
            tile_load(t, Ap, Wp, rbase, cbase, kb, K, Nr, M, sAu[buf ^ 1], sWu[buf ^ 1]);
            asm volatile("cp.async.commit_group;");
            asm volatile("cp.async.wait_group 1;");
        } else {
            asm volatile("cp.async.wait_group 0;");
        }
        __syncthreads();

        uint32_t baseA = sAu[buf];
        uint32_t baseW = sWu[buf];
#pragma unroll
        for (int s = 0; s < 2; s++) {
            uint32_t afrag[4][4];
#pragma unroll
            for (int mt = 0; mt < 4; mt++) {
                uint32_t addr = baseA + (uint32_t)((wm + mt * 16 + rA) * ASTRIDE + s * 16 + kA) * 2;
                LDM_X4(afrag[mt][0], afrag[mt][1], afrag[mt][2], afrag[mt][3], addr);
            }
            uint32_t bfrag[4][2];
#pragma unroll
            for (int np = 0; np < 2; np++) {
                uint32_t addr = baseW + (uint32_t)((wn + np * 16 + rB) * ASTRIDE + s * 16 + kB) * 2;
                uint32_t q0, q1, q2, q3;
                LDM_X4(q0, q1, q2, q3, addr);
                bfrag[np * 2][0] = q0; bfrag[np * 2][1] = q1;
                bfrag[np * 2 + 1][0] = q2; bfrag[np * 2 + 1][1] = q3;
            }
#pragma unroll
            for (int mt = 0; mt < 4; mt++)
#pragma unroll
                for (int nt = 0; nt < 4; nt++) MMA16816(acc[mt][nt], afrag[mt], bfrag[nt]);
        }
        __syncthreads();
        buf ^= 1;
    }

#pragma unroll
    for (int mt = 0; mt < 4; mt++) {
        int row0 = rbase + wm + mt * 16 + (lane >> 2);
        int row1 = row0 + 8;
#pragma unroll
        for (int nt = 0; nt < 4; nt++) {
            int col0 = cbase + wn + nt * 8 + (lane & 3) * 2;
            if (col0 < M) {
                float b0 = bias[col0];
                if (row0 < Nr) C[(size_t)row0 * M + col0] = acc[mt][nt][0] + b0;
                if (row1 < Nr) C[(size_t)row1 * M + col0] = acc[mt][nt][2] + b0;
            }
            if (col0 + 1 < M) {
                float b1 = bias[col0 + 1];
                if (row0 < Nr) C[(size_t)row0 * M + col0 + 1] = acc[mt][nt][1] + b1;
                if (row1 < Nr) C[(size_t)row1 * M + col0 + 1] = acc[mt][nt][3] + b1;
            }
        }
    }
}

// ---------------- GraphNorm: fused stats + affine apply ---------------------
#define GN_RB 64

__global__ void k_gn_stats(const float* __restrict__ h, const int* __restrict__ batch,
                           float* __restrict__ gsum, float* __restrict__ gsq) {
    int c = threadIdx.x;
    int r0 = blockIdx.x * GN_RB;
    int r1 = min(r0 + GN_RB, NN);
    int gcur = batch[r0];
    float s = 0.f, q = 0.f;
    for (int r = r0; r < r1; r++) {
        int g = batch[r];
        if (g != gcur) {
            atomicAdd(&gsum[gcur * HD + c], s);
            atomicAdd(&gsq[gcur * HD + c], q);
            s = 0.f; q = 0.f; gcur = g;
        }
        float v = h[(size_t)r * HD + c];
        s += v; q += v * v;
    }
    atomicAdd(&gsum[gcur * HD + c], s);
    atomicAdd(&gsq[gcur * HD + c], q);
}

// var = E[x^2] - alpha*(2-alpha)*mean^2 ; S = rsqrt(var+eps)*w ; T = b - alpha*mean*S
__global__ void k_gn_coef(const float* __restrict__ gsum, const float* __restrict__ gsq,
                          const float* __restrict__ invsz,
                          const float* __restrict__ w, const float* __restrict__ b,
                          const float* __restrict__ a,
                          float* __restrict__ gS, float* __restrict__ gT) {
    int i = blockIdx.x * blockDim.x + threadIdx.x;
    if (i >= NG * HD) return;
    int g = i / HD, c = i - g * HD;
    float iv = invsz[g];
    float m = gsum[i] * iv;
    float e2 = gsq[i] * iv;
    float alc = a[c];
    float var = e2 - alc * (2.f - alc) * m * m;
    float S = rsqrtf(var + EPSV) * w[c];
    gS[i] = S;
    gT[i] = b[c] - alc * m * S;
}

// out = relu(x*S + T) -> bf16 hi/lo only
__global__ void k_gn_apply2(const float* __restrict__ h, const int* __restrict__ batch,
                            const float* __restrict__ gS, const float* __restrict__ gT,
                            __nv_bfloat16* __restrict__ xh, __nv_bfloat16* __restrict__ xl) {
    int i4 = blockIdx.x * blockDim.x + threadIdx.x;
    const int n4 = NN * (HD / 4);
    if (i4 >= n4) return;
    int r = i4 >> 7;
    int c4 = (i4 & 127) * 4;
    int g = batch[r];
    float4 v = *((const float4*)h + i4);
    float4 S = *(const float4*)&gS[g * HD + c4];
    float4 T = *(const float4*)&gT[g * HD + c4];
    v.x = fmaxf(fmaf(v.x, S.x, T.x), 0.f);
    v.y = fmaxf(fmaf(v.y, S.y, T.y), 0.f);
    v.z = fmaxf(fmaf(v.z, S.z, T.z), 0.f);
    v.w = fmaxf(fmaf(v.w, S.w, T.w), 0.f);
    __nv_bfloat162 h01, h23, l01, l23;
    h01.x = __float2bfloat16_rn(v.x); h01.y = __float2bfloat16_rn(v.y);
    h23.x = __float2bfloat16_rn(v.z); h23.y = __float2bfloat16_rn(v.w);
    l01.x = __float2bfloat16_rn(v.x - __bfloat162float(h01.x));
    l01.y = __float2bfloat16_rn(v.y - __bfloat162float(h01.y));
    l23.x = __float2bfloat16_rn(v.z - __bfloat162float(h23.x));
    l23.y = __float2bfloat16_rn(v.w - __bfloat162float(h23.y));
    *(__nv_bfloat162*)(xh + (size_t)i4 * 4) = h01;
    *(__nv_bfloat162*)(xh + (size_t)i4 * 4 + 2) = h23;
    *(__nv_bfloat162*)(xl + (size_t)i4 * 4) = l01;
    *(__nv_bfloat162*)(xl + (size_t)i4 * 4 + 2) = l23;
}

// ---------------- host-side orchestration ----------------------------------
static float* symaddrf(const void* s) { void* p = nullptr; cudaGetSymbolAddress(&p, s); return (float*)p; }
static int* symaddri(const void* s) { void* p = nullptr; cudaGetSymbolAddress(&p, s); return (int*)p; }
static __nv_bfloat16* symaddrb(const void* s) { void* p = nullptr; cudaGetSymbolAddress(&p, s); return (__nv_bfloat16*)p; }

extern "C" void kernel_launch(void* const* d_in, const int* in_sizes, int n_in,
                              void* d_out, int out_size) {
    const float* x      = (const float*)d_in[0];
    const int*   ei     = (const int*)d_in[1];
    const int*   batch  = (const int*)d_in[2];
    const int*   src    = ei;
    const int*   dst    = ei + NE;

    const float* Wl[5] = {(const float*)d_in[3], (const float*)d_in[6], (const float*)d_in[9],
                          (const float*)d_in[12], (const float*)d_in[15]};
    const float* Wr[5] = {(const float*)d_in[4], (const float*)d_in[7], (const float*)d_in[10],
                          (const float*)d_in[13], (const float*)d_in[16]};
    const float* bb[5] = {(const float*)d_in[5], (const float*)d_in[8], (const float*)d_in[11],
                          (const float*)d_in[14], (const float*)d_in[17]};
    const float* gw[4] = {(const float*)d_in[18], (const float*)d_in[21], (const float*)d_in[24],
                          (const float*)d_in[27]};
    const float* gb[4] = {(const float*)d_in[19], (const float*)d_in[22], (const float*)d_in[25],
                          (const float*)d_in[28]};
    const float* ga[4] = {(const float*)d_in[20], (const float*)d_in[23], (const float*)d_in[26],
                          (const float*)d_in[29]};

    float* h1     = symaddrf(g_h1);
    int*   degi   = symaddri(g_degi);
    int*   rowptr = symaddri(g_rowptr);
    int*   cursor = symaddri(g_cursor);
    int*   csr    = symaddri(g_csr);
    float* invsz  = symaddrf(g_invsz);
    float* gsum   = symaddrf(g_gsum);
    float* gsq    = symaddrf(g_gsq);
    float* gS     = symaddrf(g_gS);
    float* gT     = symaddrf(g_gT);
    __nv_bfloat16* ah  = symaddrb(g_ah);
    __nv_bfloat16* al  = symaddrb(g_al);
    __nv_bfloat16* xh  = symaddrb(g_xh);
    __nv_bfloat16* xl  = symaddrb(g_xl);
    __nv_bfloat16* w1h = symaddrb(g_w1h);
    __nv_bfloat16* w1l = symaddrb(g_w1l);
    __nv_bfloat16* w2h = symaddrb(g_w2h);
    __nv_bfloat16* w2l = symaddrb(g_w2l);

    auto Z = [&](void* p, size_t nfloats) {
        int n4 = (int)(nfloats / 4);
        int blocks = (n4 + 255) / 256;
        if (blocks > 32768) blocks = 32768;
        k_zero4<<<blocks, 256>>>((float4*)p, n4);
    };
    auto SPLIT = [&](const float* in, __nv_bfloat16* hi, __nv_bfloat16* lo,
                     int rows, int Kin, int Kpad) {
        int total = rows * Kpad;
        int blocks = (total + 255) / 256;
        if (blocks > 65535) blocks = 65535;
        k_split<<<blocks, 256>>>(in, hi, lo, rows, Kin, Kpad);
    };

    // ---- CSR build + group sizes ----
    Z(degi, NN);
    Z(cursor, NN);
    k_count_i<<<(NE + 255) / 256, 256>>>(dst, degi, NE);
    k_scan<<<1, 1024>>>(degi, rowptr);
    k_scatter<<<(NE + 255) / 256, 256>>>(src, dst, rowptr, cursor, csr);
    k_group_sizes<<<1, 32>>>(batch, invsz);

    auto gnorm = [&](float* h, const float* w, const float* bias, const float* alpha) {
        Z(gsum, (size_t)NG * HD);
        Z(gsq, (size_t)NG * HD);
        k_gn_stats<<<(NN + GN_RB - 1) / GN_RB, HD>>>(h, batch, gsum, gsq);
        k_gn_coef<<<(NG * HD + 255) / 256, 256>>>(gsum, gsq, invsz, w, bias, alpha, gS, gT);
        k_gn_apply2<<<(NN * (HD / 4) + 255) / 256, 256>>>(h, batch, gS, gT, xh, xl);
    };

    // ---- layer 1 (50 -> 512) ----
    k_aggcsr50<<<NN, 64>>>(x, rowptr, csr, ah, al);
    SPLIT(x, xh, xl, NN, FD, FDP);
    SPLIT(Wl[0], w1h, w1l, HD, FD, FDP);
    SPLIT(Wr[0], w2h, w2l, HD, FD, FDP);
    {
        dim3 grid(HD / GBN, (NN + GBM - 1) / GBM);
        k_gemm_tc<<<grid, 256>>>(ah, al, w1h, w1l, xh, xl, w2h, w2l, bb[0], h1,
                                 NN, HD, FDP);
    }
    gnorm(h1, gw[0], gb[0], ga[0]);   // writes xh/xl = split(act1)

    // ---- layers 2..4 (512 -> 512) ----
    for (int l = 1; l <= 3; l++) {
        k_aggcsr512<<<NN, 128>>>(xh, xl, rowptr, csr, ah, al);
        SPLIT(Wl[l], w1h, w1l, HD, HD, HD);
        SPLIT(Wr[l], w2h, w2l, HD, HD, HD);
        dim3 grid(HD / GBN, (NN + GBM - 1) / GBM);
        k_gemm_tc<<<grid, 256>>>(ah, al, w1h, w1l, xh, xl, w2h, w2l, bb[l], h1,
                                 NN, HD, HD);
        gnorm(h1, gw[l], gb[l], ga[l]);
    }

    // ---- layer 5 (512 -> 121) -> d_out ----
    k_aggcsr512<<<NN, 128>>>(xh, xl, rowptr, csr, ah, al);
    SPLIT(Wl[4], w1h, w1l, OD, HD, HD);
    SPLIT(Wr[4], w2h, w2l, OD, HD, HD);
    {
        dim3 grid((OD + GBN - 1) / GBN, (NN + GBM - 1) / GBM);
        k_gemm_tc<<<grid, 256>>>(ah, al, w1h, w1l, xh, xl, w2h, w2l, bb[4],
                                 (float*)d_out, NN, OD, HD);
    }
}

// round 8
// speedup vs baseline: 2.8625x; 1.1099x over previous
#include <cuda_runtime.h>
#include <cuda_bf16.h>
#include <cstdint>
#include <math.h>

#define NN 50000
#define NE 800000
#define FD 50
#define FDP 64
#define HD 512
#define OD 121
#define NG 20
#define EPSV 1e-5f

// ---------------- scratch ---------------------------------------------------
__device__ float g_h1[(size_t)NN * HD];
__device__ int   g_degi[NN];
__device__ int   g_rowptr[NN + 1];
__device__ int   g_cursor[NN];
__device__ int   g_csr[NE];
__device__ float g_invsz[NG];
__device__ float g_gsum[NG * HD];
__device__ float g_gsq[NG * HD];
__device__ float g_gS[NG * HD];
__device__ float g_gT[NG * HD];
__device__ __nv_bfloat16 g_ah[(size_t)NN * HD];
__device__ __nv_bfloat16 g_al[(size_t)NN * HD];
__device__ __nv_bfloat16 g_xh[(size_t)NN * HD];
__device__ __nv_bfloat16 g_xl[(size_t)NN * HD];
__device__ __nv_bfloat16 g_w1h[HD * HD];
__device__ __nv_bfloat16 g_w1l[HD * HD];
__device__ __nv_bfloat16 g_w2h[HD * HD];
__device__ __nv_bfloat16 g_w2l[HD * HD];

// ---------------- utility ---------------------------------------------------
__global__ void k_zero4(float4* p, int n4) {
    int i = blockIdx.x * blockDim.x + threadIdx.x;
    int stride = gridDim.x * blockDim.x;
    for (; i < n4; i += stride) p[i] = make_float4(0.f, 0.f, 0.f, 0.f);
}

__global__ void k_count_i(const int* __restrict__ idx, int* __restrict__ cnt, int n) {
    int i = blockIdx.x * blockDim.x + threadIdx.x;
    if (i < n) atomicAdd(&cnt[idx[i]], 1);
}

__global__ void k_group_sizes(const int* __restrict__ batch, float* __restrict__ invsz) {
    int g = threadIdx.x;
    if (g >= NG) return;
    int lo = 0, hi = NN;
    while (lo < hi) { int m = (lo + hi) >> 1; if (batch[m] < g) lo = m + 1; else hi = m; }
    int lb = lo;
    lo = 0; hi = NN;
    while (lo < hi) { int m = (lo + hi) >> 1; if (batch[m] < g + 1) lo = m + 1; else hi = m; }
    invsz[g] = 1.0f / fmaxf((float)(lo - lb), 1.0f);
}

// chunked single-pass scan: each thread owns ~49 contiguous nodes
__global__ void k_scan2(const int* __restrict__ deg, int* __restrict__ rowptr) {
    __shared__ int sh[1024];
    int tid = threadIdx.x;
    const int CH = (NN + 1023) / 1024;
    int start = tid * CH, end = min(start + CH, NN);
    int s = 0;
    for (int i = start; i < end; i++) s += deg[i];
    sh[tid] = s;
    __syncthreads();
    for (int d = 1; d < 1024; d <<= 1) {
        int v = (tid >= d) ? sh[tid - d] : 0;
        __syncthreads();
        sh[tid] += v;
        __syncthreads();
    }
    int off = sh[tid] - s;
    for (int i = start; i < end; i++) { rowptr[i] = off; off += deg[i]; }
    if (tid == 1023) rowptr[NN] = sh[1023];
}

__global__ void k_scatter(const int* __restrict__ src, const int* __restrict__ dst,
                          const int* __restrict__ rowptr, int* __restrict__ cursor,
                          int* __restrict__ csr) {
    int e = blockIdx.x * blockDim.x + threadIdx.x;
    if (e >= NE) return;
    int d = dst[e];
    int p = atomicAdd(&cursor[d], 1);
    csr[rowptr[d] + p] = src[e];
}

__global__ void k_split(const float* __restrict__ in,
                        __nv_bfloat16* __restrict__ hi, __nv_bfloat16* __restrict__ lo,
                        int rows, int Kin, int Kpad) {
    int idx = blockIdx.x * blockDim.x + threadIdx.x;
    int total = rows * Kpad;
    int stride = gridDim.x * blockDim.x;
    for (; idx < total; idx += stride) {
        int r = idx / Kpad;
        int c = idx - r * Kpad;
        float v = (c < Kin) ? in[(size_t)r * Kin + c] : 0.f;
        __nv_bfloat16 h = __float2bfloat16_rn(v);
        hi[idx] = h;
        lo[idx] = __float2bfloat16_rn(v - __bfloat162float(h));
    }
}

// ---------------- CSR aggregation ------------------------------------------
__device__ __forceinline__ void addb4(float4& a, uint2 u) {
    __nv_bfloat162 p0 = *reinterpret_cast<__nv_bfloat162*>(&u.x);
    __nv_bfloat162 p1 = *reinterpret_cast<__nv_bfloat162*>(&u.y);
    a.x += __low2float(p0); a.y += __high2float(p0);
    a.z += __low2float(p1); a.w += __high2float(p1);
}

__global__ __launch_bounds__(128)
void k_aggcsr512(const __nv_bfloat16* __restrict__ xh, const __nv_bfloat16* __restrict__ xl,
                 const int* __restrict__ rowptr, const int* __restrict__ csr,
                 __nv_bfloat16* __restrict__ ah, __nv_bfloat16* __restrict__ al) {
    int node = blockIdx.x;
    int c = threadIdx.x * 4;
    int start = __ldg(&rowptr[node]);
    int end = __ldg(&rowptr[node + 1]);
    float4 acc = make_float4(0.f, 0.f, 0.f, 0.f);
    int j = start;
    for (; j + 1 < end; j += 2) {
        int s0 = __ldg(&csr[j]);
        int s1 = __ldg(&csr[j + 1]);
        uint2 h0 = *(const uint2*)(xh + (size_t)s0 * HD + c);
        uint2 l0 = *(const uint2*)(xl + (size_t)s0 * HD + c);
        uint2 h1 = *(const uint2*)(xh + (size_t)s1 * HD + c);
        uint2 l1 = *(const uint2*)(xl + (size_t)s1 * HD + c);
        addb4(acc, h0); addb4(acc, l0);
        addb4(acc, h1); addb4(acc, l1);
    }
    if (j < end) {
        int s0 = __ldg(&csr[j]);
        uint2 h0 = *(const uint2*)(xh + (size_t)s0 * HD + c);
        uint2 l0 = *(const uint2*)(xl + (size_t)s0 * HD + c);
        addb4(acc, h0); addb4(acc, l0);
    }
    float inv = 1.0f / fmaxf((float)(end - start), 1.0f);
    acc.x *= inv; acc.y *= inv; acc.z *= inv; acc.w *= inv;
    __nv_bfloat162 h01, h23, l01, l23;
    h01.x = __float2bfloat16_rn(acc.x); h01.y = __float2bfloat16_rn(acc.y);
    h23.x = __float2bfloat16_rn(acc.z); h23.y = __float2bfloat16_rn(acc.w);
    l01.x = __float2bfloat16_rn(acc.x - __bfloat162float(h01.x));
    l01.y = __float2bfloat16_rn(acc.y - __bfloat162float(h01.y));
    l23.x = __float2bfloat16_rn(acc.z - __bfloat162float(h23.x));
    l23.y = __float2bfloat16_rn(acc.w - __bfloat162float(h23.y));
    __nv_bfloat162* ph = (__nv_bfloat162*)(ah + (size_t)node * HD + c);
    __nv_bfloat162* pl = (__nv_bfloat162*)(al + (size_t)node * HD + c);
    ph[0] = h01; ph[1] = h23;
    pl[0] = l01; pl[1] = l23;
}

__global__ __launch_bounds__(64)
void k_aggcsr50(const float* __restrict__ x,
                const int* __restrict__ rowptr, const int* __restrict__ csr,
                __nv_bfloat16* __restrict__ ah, __nv_bfloat16* __restrict__ al) {
    int node = blockIdx.x;
    int c = threadIdx.x;
    int start = __ldg(&rowptr[node]);
    int end = __ldg(&rowptr[node + 1]);
    float acc = 0.f;
    if (c < FD) {
        for (int j = start; j < end; j++) {
            int s = __ldg(&csr[j]);
            acc += __ldg(&x[(size_t)s * FD + c]);
        }
    }
    float inv = 1.0f / fmaxf((float)(end - start), 1.0f);
    float v = acc * inv;
    __nv_bfloat16 h = __float2bfloat16_rn(v);
    ah[(size_t)node * FDP + c] = h;
    al[(size_t)node * FDP + c] = __float2bfloat16_rn(v - __bfloat162float(h));
}

// ---------------- tensor-core dual GEMM (mma.sync, 4-tile K-block) ----------
// C = Ah@Wh1^T + Al@Wh1^T + Ah@Wl1^T + Xh@Wh2^T + Xl@Wh2^T + Xh@Wl2^T + bias
// Per 32-wide K-block: load Ah/Al/Wh/Wl tiles once, run 3 MMA passes from smem.
#define GBM 128
#define GBN 128
#define GBK 32
#define ASTRIDE 40
#define TILE_B (GBM * ASTRIDE * 2)     // 10240 bytes per tile
#define BUF_B (4 * TILE_B)             // 40960 bytes per K-block buffer
#define GEMM_DYN (2 * BUF_B)           // 81920 bytes

#define LDM_X4(r0_, r1_, r2_, r3_, addr_)                                        \
    asm volatile("ldmatrix.sync.aligned.m8n8.x4.shared.b16 {%0,%1,%2,%3}, [%4];" \
                 : "=r"(r0_), "=r"(r1_), "=r"(r2_), "=r"(r3_) : "r"(addr_))

#define MMA16816(c_, a_, b_)                                                   \
    asm volatile("mma.sync.aligned.m16n8k16.row.col.f32.bf16.bf16.f32 "        \
                 "{%0,%1,%2,%3}, {%4,%5,%6,%7}, {%8,%9}, {%0,%1,%2,%3};"       \
                 : "+f"(c_[0]), "+f"(c_[1]), "+f"(c_[2]), "+f"(c_[3])          \
                 : "r"(a_[0]), "r"(a_[1]), "r"(a_[2]), "r"(a_[3]),             \
                   "r"(b_[0]), "r"(b_[1]))

__device__ __forceinline__ void cp16(uint32_t dst, const void* src, int okbytes) {
    asm volatile("cp.async.cg.shared.global [%0], [%1], 16, %2;"
                 :: "r"(dst), "l"(src), "r"(okbytes));
}

// load one K-block: 4 tiles (Ah, Al, Wh, Wl), each 128 rows x 32 cols bf16
__device__ __forceinline__ void load_block4(const __nv_bfloat16* AH, const __nv_bfloat16* AL,
                                            const __nv_bfloat16* WH, const __nv_bfloat16* WL,
                                            int rbase, int cbase, int kb, int K,
                                            int Nr, int M, uint32_t sb) {
    int t = threadIdx.x;
#pragma unroll
    for (int p = 0; p < 8; p++) {
        int idx = t + p * 256;           // 0..2047
        int tile = idx >> 9;             // 0..3
        int i9 = idx & 511;
        int row = i9 >> 2;
        int seg = i9 & 3;
        uint32_t soff = sb + (uint32_t)tile * TILE_B + (uint32_t)(row * ASTRIDE + seg * 8) * 2;
        const __nv_bfloat16* base;
        int gr, lim;
        if (tile < 2) { gr = rbase + row; lim = Nr; base = tile ? AL : AH; }
        else          { gr = cbase + row; lim = M;  base = (tile == 2) ? WH : WL; }
        int ok = (gr < lim) ? 16 : 0;
        int gg = (gr < lim) ? gr : 0;
        cp16(soff, base + (size_t)gg * K + kb + seg * 8, ok);
    }
}

__global__ __launch_bounds__(256, 2)
void k_gemm_tc(const __nv_bfloat16* __restrict__ Ah1, const __nv_bfloat16* __restrict__ Al1,
               const __nv_bfloat16* __restrict__ Wh1, const __nv_bfloat16* __restrict__ Wl1,
               const __nv_bfloat16* __restrict__ Ah2, const __nv_bfloat16* __restrict__ Al2,
               const __nv_bfloat16* __restrict__ Wh2, const __nv_bfloat16* __restrict__ Wl2,
               const float* __restrict__ bias, float* __restrict__ C,
               int Nr, int M, int K) {
    extern __shared__ __align__(16) char dyn[];
    uint32_t sbase = (uint32_t)__cvta_generic_to_shared(dyn);

    int t = threadIdx.x;
    int lane = t & 31;
    int wid = t >> 5;
    int wm = (wid >> 2) * 64;
    int wn = (wid & 3) * 32;
    int rbase = blockIdx.y * GBM;
    int cbase = blockIdx.x * GBN;

    float acc[4][4][4];
#pragma unroll
    for (int i = 0; i < 4; i++)
#pragma unroll
        for (int j = 0; j < 4; j++)
#pragma unroll
            for (int q = 0; q < 4; q++) acc[i][j][q] = 0.f;

    const int KB = K / GBK;
    const int total = 2 * KB;            // two operand passes (agg@W1, x@W2)

    auto pick = [&](int blk, const __nv_bfloat16*& AH, const __nv_bfloat16*& AL,
                    const __nv_bfloat16*& WH, const __nv_bfloat16*& WL, int& kb) {
        int pass = blk / KB;
        kb = (blk - pass * KB) * GBK;
        if (pass == 0) { AH = Ah1; AL = Al1; WH = Wh1; WL = Wl1; }
        else           { AH = Ah2; AL = Al2; WH = Wh2; WL = Wl2; }
    };

    int g = lane >> 3;
    int rA = (lane & 7) + ((g & 1) << 3);
    int kA = (g >> 1) << 3;
    int rB = (lane & 7) + ((g >> 1) << 3);
    int kB = (g & 1) << 3;

    {
        const __nv_bfloat16 *AH, *AL, *WH, *WL; int kb;
        pick(0, AH, AL, WH, WL, kb);
        load_block4(AH, AL, WH, WL, rbase, cbase, kb, K, Nr, M, sbase);
        asm volatile("cp.async.commit_group;");
    }

    for (int it = 0; it < total; it++) {
        if (it + 1 < total) {
            const __nv_bfloat16 *AH, *AL, *WH, *WL; int kb;
            pick(it + 1, AH, AL, WH, WL, kb);
            load_block4(AH, AL, WH, WL, rbase, cbase, kb, K, Nr, M,
                        sbase + ((it + 1) & 1) * BUF_B);
            asm volatile("cp.async.commit_group;");
            asm volatile("cp.async.wait_group 1;");
        } else {
            asm volatile("cp.async.wait_group 0;");
        }
        __syncthreads();

        uint32_t buf = sbase + (it & 1) * BUF_B;
#pragma unroll
        for (int pass = 0; pass < 3; pass++) {
            uint32_t baseA = buf + ((pass == 1) ? TILE_B : 0);
            uint32_t baseW = buf + ((pass == 2) ? 3 * TILE_B : 2 * TILE_B);
#pragma unroll
            for (int s = 0; s < 2; s++) {
                uint32_t afrag[4][4];
#pragma unroll
                for (int mt = 0; mt < 4; mt++) {
                    uint32_t addr = baseA + (uint32_t)((wm + mt * 16 + rA) * ASTRIDE + s * 16 + kA) * 2;
                    LDM_X4(afrag[mt][0], afrag[mt][1], afrag[mt][2], afrag[mt][3], addr);
                }
                uint32_t bfrag[4][2];
#pragma unroll
                for (int np = 0; np < 2; np++) {
                    uint32_t addr = baseW + (uint32_t)((wn + np * 16 + rB) * ASTRIDE + s * 16 + kB) * 2;
                    uint32_t q0, q1, q2, q3;
                    LDM_X4(q0, q1, q2, q3, addr);
                    bfrag[np * 2][0] = q0; bfrag[np * 2][1] = q1;
                    bfrag[np * 2 + 1][0] = q2; bfrag[np * 2 + 1][1] = q3;
                }
#pragma unroll
                for (int mt = 0; mt < 4; mt++)
#pragma unroll
                    for (int nt = 0; nt < 4; nt++) MMA16816(acc[mt][nt], afrag[mt], bfrag[nt]);
            }
        }
        __syncthreads();
    }

#pragma unroll
    for (int mt = 0; mt < 4; mt++) {
        int row0 = rbase + wm + mt * 16 + (lane >> 2);
        int row1 = row0 + 8;
#pragma unroll
        for (int nt = 0; nt < 4; nt++) {
            int col0 = cbase + wn + nt * 8 + (lane & 3) * 2;
            if (col0 < M) {
                float b0 = bias[col0];
                if (row0 < Nr) C[(size_t)row0 * M + col0] = acc[mt][nt][0] + b0;
                if (row1 < Nr) C[(size_t)row1 * M + col0] = acc[mt][nt][2] + b0;
            }
            if (col0 + 1 < M) {
                float b1 = bias[col0 + 1];
                if (row0 < Nr) C[(size_t)row0 * M + col0 + 1] = acc[mt][nt][1] + b1;
                if (row1 < Nr) C[(size_t)row1 * M + col0 + 1] = acc[mt][nt][3] + b1;
            }
        }
    }
}

// ---------------- GraphNorm ------------------------------------------------
#define GN_RB 64

__global__ void k_gn_stats(const float* __restrict__ h, const int* __restrict__ batch,
                           float* __restrict__ gsum, float* __restrict__ gsq) {
    int c = threadIdx.x;
    int r0 = blockIdx.x * GN_RB;
    int r1 = min(r0 + GN_RB, NN);
    int gcur = batch[r0];
    float s = 0.f, q = 0.f;
    for (int r = r0; r < r1; r++) {
        int g = batch[r];
        if (g != gcur) {
            atomicAdd(&gsum[gcur * HD + c], s);
            atomicAdd(&gsq[gcur * HD + c], q);
            s = 0.f; q = 0.f; gcur = g;
        }
        float v = h[(size_t)r * HD + c];
        s += v; q += v * v;
    }
    atomicAdd(&gsum[gcur * HD + c], s);
    atomicAdd(&gsq[gcur * HD + c], q);
}

__global__ void k_gn_coef(const float* __restrict__ gsum, const float* __restrict__ gsq,
                          const float* __restrict__ invsz,
                          const float* __restrict__ w, const float* __restrict__ b,
                          const float* __restrict__ a,
                          float* __restrict__ gS, float* __restrict__ gT) {
    int i = blockIdx.x * blockDim.x + threadIdx.x;
    if (i >= NG * HD) return;
    int g = i / HD, c = i - g * HD;
    float iv = invsz[g];
    float m = gsum[i] * iv;
    float e2 = gsq[i] * iv;
    float alc = a[c];
    float var = e2 - alc * (2.f - alc) * m * m;
    float S = rsqrtf(var + EPSV) * w[c];
    gS[i] = S;
    gT[i] = b[c] - alc * m * S;
}

__global__ void k_gn_apply2(const float* __restrict__ h, const int* __restrict__ batch,
                            const float* __restrict__ gS, const float* __restrict__ gT,
                            __nv_bfloat16* __restrict__ xh, __nv_bfloat16* __restrict__ xl) {
    int i4 = blockIdx.x * blockDim.x + threadIdx.x;
    const int n4 = NN * (HD / 4);
    if (i4 >= n4) return;
    int r = i4 >> 7;
    int c4 = (i4 & 127) * 4;
    int g = batch[r];
    float4 v = *((const float4*)h + i4);
    float4 S = *(const float4*)&gS[g * HD + c4];
    float4 T = *(const float4*)&gT[g * HD + c4];
    v.x = fmaxf(fmaf(v.x, S.x, T.x), 0.f);
    v.y = fmaxf(fmaf(v.y, S.y, T.y), 0.f);
    v.z = fmaxf(fmaf(v.z, S.z, T.z), 0.f);
    v.w = fmaxf(fmaf(v.w, S.w, T.w), 0.f);
    __nv_bfloat162 h01, h23, l01, l23;
    h01.x = __float2bfloat16_rn(v.x); h01.y = __float2bfloat16_rn(v.y);
    h23.x = __float2bfloat16_rn(v.z); h23.y = __float2bfloat16_rn(v.w);
    l01.x = __float2bfloat16_rn(v.x - __bfloat162float(h01.x));
    l01.y = __float2bfloat16_rn(v.y - __bfloat162float(h01.y));
    l23.x = __float2bfloat16_rn(v.z - __bfloat162float(h23.x));
    l23.y = __float2bfloat16_rn(v.w - __bfloat162float(h23.y));
    *(__nv_bfloat162*)(xh + (size_t)i4 * 4) = h01;
    *(__nv_bfloat162*)(xh + (size_t)i4 * 4 + 2) = h23;
    *(__nv_bfloat162*)(xl + (size_t)i4 * 4) = l01;
    *(__nv_bfloat162*)(xl + (size_t)i4 * 4 + 2) = l23;
}

// ---------------- host-side orchestration ----------------------------------
static float* symaddrf(const void* s) { void* p = nullptr; cudaGetSymbolAddress(&p, s); return (float*)p; }
static int* symaddri(const void* s) { void* p = nullptr; cudaGetSymbolAddress(&p, s); return (int*)p; }
static __nv_bfloat16* symaddrb(const void* s) { void* p = nullptr; cudaGetSymbolAddress(&p, s); return (__nv_bfloat16*)p; }

extern "C" void kernel_launch(void* const* d_in, const int* in_sizes, int n_in,
                              void* d_out, int out_size) {
    const float* x      = (const float*)d_in[0];
    const int*   ei     = (const int*)d_in[1];
    const int*   batch  = (const int*)d_in[2];
    const int*   src    = ei;
    const int*   dst    = ei + NE;

    const float* Wl[5] = {(const float*)d_in[3], (const float*)d_in[6], (const float*)d_in[9],
                          (const float*)d_in[12], (const float*)d_in[15]};
    const float* Wr[5] = {(const float*)d_in[4], (const float*)d_in[7], (const float*)d_in[10],
                          (const float*)d_in[13], (const float*)d_in[16]};
    const float* bb[5] = {(const float*)d_in[5], (const float*)d_in[8], (const float*)d_in[11],
                          (const float*)d_in[14], (const float*)d_in[17]};
    const float* gw[4] = {(const float*)d_in[18], (const float*)d_in[21], (const float*)d_in[24],
                          (const float*)d_in[27]};
    const float* gb[4] = {(const float*)d_in[19], (const float*)d_in[22], (const float*)d_in[25],
                          (const float*)d_in[28]};
    const float* ga[4] = {(const float*)d_in[20], (const float*)d_in[23], (const float*)d_in[26],
                          (const float*)d_in[29]};

    float* h1     = symaddrf(g_h1);
    int*   degi   = symaddri(g_degi);
    int*   rowptr = symaddri(g_rowptr);
    int*   cursor = symaddri(g_cursor);
    int*   csr    = symaddri(g_csr);
    float* invsz  = symaddrf(g_invsz);
    float* gsum   = symaddrf(g_gsum);
    float* gsq    = symaddrf(g_gsq);
    float* gS     = symaddrf(g_gS);
    float* gT     = symaddrf(g_gT);
    __nv_bfloat16* ah  = symaddrb(g_ah);
    __nv_bfloat16* al  = symaddrb(g_al);
    __nv_bfloat16* xh  = symaddrb(g_xh);
    __nv_bfloat16* xl  = symaddrb(g_xl);
    __nv_bfloat16* w1h = symaddrb(g_w1h);
    __nv_bfloat16* w1l = symaddrb(g_w1l);
    __nv_bfloat16* w2h = symaddrb(g_w2h);
    __nv_bfloat16* w2l = symaddrb(g_w2l);

    cudaFuncSetAttribute(k_gemm_tc, cudaFuncAttributeMaxDynamicSharedMemorySize, GEMM_DYN);

    auto Z = [&](void* p, size_t nfloats) {
        int n4 = (int)(nfloats / 4);
        int blocks = (n4 + 255) / 256;
        if (blocks > 32768) blocks = 32768;
        k_zero4<<<blocks, 256>>>((float4*)p, n4);
    };
    auto SPLIT = [&](const float* in, __nv_bfloat16* hi, __nv_bfloat16* lo,
                     int rows, int Kin, int Kpad) {
        int total = rows * Kpad;
        int blocks = (total + 255) / 256;
        if (blocks > 65535) blocks = 65535;
        k_split<<<blocks, 256>>>(in, hi, lo, rows, Kin, Kpad);
    };
    auto GEMM = [&](const float* bias, float* C, int Mout, int K) {
        dim3 grid((Mout + GBN - 1) / GBN, (NN + GBM - 1) / GBM);
        k_gemm_tc<<<grid, 256, GEMM_DYN>>>(ah, al, w1h, w1l, xh, xl, w2h, w2l,
                                           bias, C, NN, Mout, K);
    };

    // ---- CSR build + group sizes ----
    Z(degi, NN);
    Z(cursor, NN);
    k_count_i<<<(NE + 255) / 256, 256>>>(dst, degi, NE);
    k_scan2<<<1, 1024>>>(degi, rowptr);
    k_scatter<<<(NE + 255) / 256, 256>>>(src, dst, rowptr, cursor, csr);
    k_group_sizes<<<1, 32>>>(batch, invsz);

    auto gnorm = [&](float* h, const float* w, const float* bias, const float* alpha) {
        Z(gsum, (size_t)NG * HD);
        Z(gsq, (size_t)NG * HD);
        k_gn_stats<<<(NN + GN_RB - 1) / GN_RB, HD>>>(h, batch, gsum, gsq);
        k_gn_coef<<<(NG * HD + 255) / 256, 256>>>(gsum, gsq, invsz, w, bias, alpha, gS, gT);
        k_gn_apply2<<<(NN * (HD / 4) + 255) / 256, 256>>>(h, batch, gS, gT, xh, xl);
    };

    // ---- layer 1 (50 -> 512) ----
    k_aggcsr50<<<NN, 64>>>(x, rowptr, csr, ah, al);
    SPLIT(x, xh, xl, NN, FD, FDP);
    SPLIT(Wl[0], w1h, w1l, HD, FD, FDP);
    SPLIT(Wr[0], w2h, w2l, HD, FD, FDP);
    GEMM(bb[0], h1, HD, FDP);
    gnorm(h1, gw[0], gb[0], ga[0]);

    // ---- layers 2..4 (512 -> 512) ----
    for (int l = 1; l <= 3; l++) {
        k_aggcsr512<<<NN, 128>>>(xh, xl, rowptr, csr, ah, al);
        SPLIT(Wl[l], w1h, w1l, HD, HD, HD);
        SPLIT(Wr[l], w2h, w2l, HD, HD, HD);
        GEMM(bb[l], h1, HD, HD);
        gnorm(h1, gw[l], gb[l], ga[l]);
    }

    // ---- layer 5 (512 -> 121) -> d_out ----
    k_aggcsr512<<<NN, 128>>>(xh, xl, rowptr, csr, ah, al);
    SPLIT(Wl[4], w1h, w1l, OD, HD, HD);
    SPLIT(Wr[4], w2h, w2l, OD, HD, HD);
    GEMM(bb[4], (float*)d_out, OD, HD);
}

// round 9
// speedup vs baseline: 2.9864x; 1.0433x over previous
#include <cuda_runtime.h>
#include <cuda_bf16.h>
#include <cstdint>
#include <math.h>

#define NN 50000
#define NE 800000
#define FD 50
#define FDP 64
#define HD 512
#define OD 121
#define NG 20
#define EPSV 1e-5f

// ---------------- scratch ---------------------------------------------------
__device__ float g_h1[(size_t)NN * HD];
__device__ int   g_degi[NN];
__device__ int   g_rowptr[NN + 1];
__device__ int   g_cursor[NN];
__device__ int   g_csr[NE];
__device__ float g_invsz[NG];
__device__ float g_gsum[NG * HD];
__device__ float g_gsq[NG * HD];
__device__ float g_gS[NG * HD];
__device__ float g_gT[NG * HD];
__device__ __nv_bfloat16 g_ah[(size_t)NN * HD];
__device__ __nv_bfloat16 g_al[(size_t)NN * HD];
__device__ __nv_bfloat16 g_xh[(size_t)NN * HD];
__device__ __nv_bfloat16 g_xl[(size_t)NN * HD];
__device__ __nv_bfloat16 g_w1h[HD * HD];
__device__ __nv_bfloat16 g_w1l[HD * HD];
__device__ __nv_bfloat16 g_w2h[HD * HD];
__device__ __nv_bfloat16 g_w2l[HD * HD];

// ---------------- utility ---------------------------------------------------
__global__ void k_zero4(float4* p, int n4) {
    int i = blockIdx.x * blockDim.x + threadIdx.x;
    int stride = gridDim.x * blockDim.x;
    for (; i < n4; i += stride) p[i] = make_float4(0.f, 0.f, 0.f, 0.f);
}

__global__ void k_count_i(const int* __restrict__ idx, int* __restrict__ cnt, int n) {
    int i = blockIdx.x * blockDim.x + threadIdx.x;
    if (i < n) atomicAdd(&cnt[idx[i]], 1);
}

__global__ void k_group_sizes(const int* __restrict__ batch, float* __restrict__ invsz) {
    int g = threadIdx.x;
    if (g >= NG) return;
    int lo = 0, hi = NN;
    while (lo < hi) { int m = (lo + hi) >> 1; if (batch[m] < g) lo = m + 1; else hi = m; }
    int lb = lo;
    lo = 0; hi = NN;
    while (lo < hi) { int m = (lo + hi) >> 1; if (batch[m] < g + 1) lo = m + 1; else hi = m; }
    invsz[g] = 1.0f / fmaxf((float)(lo - lb), 1.0f);
}

// chunked single-pass scan: each thread owns ~49 contiguous nodes
__global__ void k_scan2(const int* __restrict__ deg, int* __restrict__ rowptr) {
    __shared__ int sh[1024];
    int tid = threadIdx.x;
    const int CH = (NN + 1023) / 1024;
    int start = tid * CH, end = min(start + CH, NN);
    int s = 0;
    for (int i = start; i < end; i++) s += deg[i];
    sh[tid] = s;
    __syncthreads();
    for (int d = 1; d < 1024; d <<= 1) {
        int v = (tid >= d) ? sh[tid - d] : 0;
        __syncthreads();
        sh[tid] += v;
        __syncthreads();
    }
    int off = sh[tid] - s;
    for (int i = start; i < end; i++) { rowptr[i] = off; off += deg[i]; }
    if (tid == 1023) rowptr[NN] = sh[1023];
}

__global__ void k_scatter(const int* __restrict__ src, const int* __restrict__ dst,
                          const int* __restrict__ rowptr, int* __restrict__ cursor,
                          int* __restrict__ csr) {
    int e = blockIdx.x * blockDim.x + threadIdx.x;
    if (e >= NE) return;
    int d = dst[e];
    int p = atomicAdd(&cursor[d], 1);
    csr[rowptr[d] + p] = src[e];
}

__global__ void k_split(const float* __restrict__ in,
                        __nv_bfloat16* __restrict__ hi, __nv_bfloat16* __restrict__ lo,
                        int rows, int Kin, int Kpad) {
    int idx = blockIdx.x * blockDim.x + threadIdx.x;
    int total = rows * Kpad;
    int stride = gridDim.x * blockDim.x;
    for (; idx < total; idx += stride) {
        int r = idx / Kpad;
        int c = idx - r * Kpad;
        float v = (c < Kin) ? in[(size_t)r * Kin + c] : 0.f;
        __nv_bfloat16 h = __float2bfloat16_rn(v);
        hi[idx] = h;
        lo[idx] = __float2bfloat16_rn(v - __bfloat162float(h));
    }
}

// ---------------- CSR aggregation ------------------------------------------
__device__ __forceinline__ void addb4(float4& a, uint2 u) {
    __nv_bfloat162 p0 = *reinterpret_cast<__nv_bfloat162*>(&u.x);
    __nv_bfloat162 p1 = *reinterpret_cast<__nv_bfloat162*>(&u.y);
    a.x += __low2float(p0); a.y += __high2float(p0);
    a.z += __low2float(p1); a.w += __high2float(p1);
}

__global__ __launch_bounds__(128)
void k_aggcsr512(const __nv_bfloat16* __restrict__ xh, const __nv_bfloat16* __restrict__ xl,
                 const int* __restrict__ rowptr, const int* __restrict__ csr,
                 __nv_bfloat16* __restrict__ ah, __nv_bfloat16* __restrict__ al) {
    int node = blockIdx.x;
    int c = threadIdx.x * 4;
    int start = __ldg(&rowptr[node]);
    int end = __ldg(&rowptr[node + 1]);
    float4 acc = make_float4(0.f, 0.f, 0.f, 0.f);
    int j = start;
    for (; j + 1 < end; j += 2) {
        int s0 = __ldg(&csr[j]);
        int s1 = __ldg(&csr[j + 1]);
        uint2 h0 = *(const uint2*)(xh + (size_t)s0 * HD + c);
        uint2 l0 = *(const uint2*)(xl + (size_t)s0 * HD + c);
        uint2 h1 = *(const uint2*)(xh + (size_t)s1 * HD + c);
        uint2 l1 = *(const uint2*)(xl + (size_t)s1 * HD + c);
        addb4(acc, h0); addb4(acc, l0);
        addb4(acc, h1); addb4(acc, l1);
    }
    if (j < end) {
        int s0 = __ldg(&csr[j]);
        uint2 h0 = *(const uint2*)(xh + (size_t)s0 * HD + c);
        uint2 l0 = *(const uint2*)(xl + (size_t)s0 * HD + c);
        addb4(acc, h0); addb4(acc, l0);
    }
    float inv = 1.0f / fmaxf((float)(end - start), 1.0f);
    acc.x *= inv; acc.y *= inv; acc.z *= inv; acc.w *= inv;
    __nv_bfloat162 h01, h23, l01, l23;
    h01.x = __float2bfloat16_rn(acc.x); h01.y = __float2bfloat16_rn(acc.y);
    h23.x = __float2bfloat16_rn(acc.z); h23.y = __float2bfloat16_rn(acc.w);
    l01.x = __float2bfloat16_rn(acc.x - __bfloat162float(h01.x));
    l01.y = __float2bfloat16_rn(acc.y - __bfloat162float(h01.y));
    l23.x = __float2bfloat16_rn(acc.z - __bfloat162float(h23.x));
    l23.y = __float2bfloat16_rn(acc.w - __bfloat162float(h23.y));
    __nv_bfloat162* ph = (__nv_bfloat162*)(ah + (size_t)node * HD + c);
    __nv_bfloat162* pl = (__nv_bfloat162*)(al + (size_t)node * HD + c);
    ph[0] = h01; ph[1] = h23;
    pl[0] = l01; pl[1] = l23;
}

__global__ __launch_bounds__(64)
void k_aggcsr50(const float* __restrict__ x,
                const int* __restrict__ rowptr, const int* __restrict__ csr,
                __nv_bfloat16* __restrict__ ah, __nv_bfloat16* __restrict__ al) {
    int node = blockIdx.x;
    int c = threadIdx.x;
    int start = __ldg(&rowptr[node]);
    int end = __ldg(&rowptr[node + 1]);
    float acc = 0.f;
    if (c < FD) {
        for (int j = start; j < end; j++) {
            int s = __ldg(&csr[j]);
            acc += __ldg(&x[(size_t)s * FD + c]);
        }
    }
    float inv = 1.0f / fmaxf((float)(end - start), 1.0f);
    float v = acc * inv;
    __nv_bfloat16 h = __float2bfloat16_rn(v);
    ah[(size_t)node * FDP + c] = h;
    al[(size_t)node * FDP + c] = __float2bfloat16_rn(v - __bfloat162float(h));
}

// ---------------- tensor-core dual GEMM (mma.sync, fragment reuse) ----------
// C = Ah@Wh1^T + Al@Wh1^T + Ah@Wl1^T + Xh@Wh2^T + Xl@Wh2^T + Xh@Wl2^T + bias
// Per 32-wide K-block: load Ah/Al/Wh/Wl tiles once; fragments loaded once and
// reused across the three split terms (order: Ah*Wh, Ah*Wl, Al*Wh).
#define GBM 128
#define GBN 128
#define GBK 32
#define ASTRIDE 40
#define TILE_B (GBM * ASTRIDE * 2)     // 10240 bytes per tile
#define BUF_B (4 * TILE_B)             // 40960 bytes per K-block buffer
#define GEMM_DYN (2 * BUF_B)           // 81920 bytes

#define LDM_X4(r0_, r1_, r2_, r3_, addr_)                                        \
    asm volatile("ldmatrix.sync.aligned.m8n8.x4.shared.b16 {%0,%1,%2,%3}, [%4];" \
                 : "=r"(r0_), "=r"(r1_), "=r"(r2_), "=r"(r3_) : "r"(addr_))

#define MMA16816(c_, a_, b_)                                                   \
    asm volatile("mma.sync.aligned.m16n8k16.row.col.f32.bf16.bf16.f32 "        \
                 "{%0,%1,%2,%3}, {%4,%5,%6,%7}, {%8,%9}, {%0,%1,%2,%3};"       \
                 : "+f"(c_[0]), "+f"(c_[1]), "+f"(c_[2]), "+f"(c_[3])          \
                 : "r"(a_[0]), "r"(a_[1]), "r"(a_[2]), "r"(a_[3]),             \
                   "r"(b_[0]), "r"(b_[1]))

__device__ __forceinline__ void cp16(uint32_t dst, const void* src, int okbytes) {
    asm volatile("cp.async.cg.shared.global [%0], [%1], 16, %2;"
                 :: "r"(dst), "l"(src), "r"(okbytes));
}

// load one K-block: 4 tiles (Ah, Al, Wh, Wl), each 128 rows x 32 cols bf16
__device__ __forceinline__ void load_block4(const __nv_bfloat16* AH, const __nv_bfloat16* AL,
                                            const __nv_bfloat16* WH, const __nv_bfloat16* WL,
                                            int rbase, int cbase, int kb, int K,
                                            int Nr, int M, uint32_t sb) {
    int t = threadIdx.x;
#pragma unroll
    for (int p = 0; p < 8; p++) {
        int idx = t + p * 256;           // 0..2047
        int tile = idx >> 9;             // 0..3
        int i9 = idx & 511;
        int row = i9 >> 2;
        int seg = i9 & 3;
        uint32_t soff = sb + (uint32_t)tile * TILE_B + (uint32_t)(row * ASTRIDE + seg * 8) * 2;
        const __nv_bfloat16* base;
        int gr, lim;
        if (tile < 2) { gr = rbase + row; lim = Nr; base = tile ? AL : AH; }
        else          { gr = cbase + row; lim = M;  base = (tile == 2) ? WH : WL; }
        int ok = (gr < lim) ? 16 : 0;
        int gg = (gr < lim) ? gr : 0;
        cp16(soff, base + (size_t)gg * K + kb + seg * 8, ok);
    }
}

__global__ __launch_bounds__(256, 2)
void k_gemm_tc(const __nv_bfloat16* __restrict__ Ah1, const __nv_bfloat16* __restrict__ Al1,
               const __nv_bfloat16* __restrict__ Wh1, const __nv_bfloat16* __restrict__ Wl1,
               const __nv_bfloat16* __restrict__ Ah2, const __nv_bfloat16* __restrict__ Al2,
               const __nv_bfloat16* __restrict__ Wh2, const __nv_bfloat16* __restrict__ Wl2,
               const float* __restrict__ bias, float* __restrict__ C,
               int Nr, int M, int K) {
    extern __shared__ __align__(16) char dyn[];
    uint32_t sbase = (uint32_t)__cvta_generic_to_shared(dyn);

    int t = threadIdx.x;
    int lane = t & 31;
    int wid = t >> 5;
    int wm = (wid >> 2) * 64;
    int wn = (wid & 3) * 32;
    int rbase = blockIdx.y * GBM;
    int cbase = blockIdx.x * GBN;

    float acc[4][4][4];
#pragma unroll
    for (int i = 0; i < 4; i++)
#pragma unroll
        for (int j = 0; j < 4; j++)
#pragma unroll
            for (int q = 0; q < 4; q++) acc[i][j][q] = 0.f;

    const int KB = K / GBK;
    const int total = 2 * KB;            // two operand passes (agg@W1, x@W2)

    auto pick = [&](int blk, const __nv_bfloat16*& AH, const __nv_bfloat16*& AL,
                    const __nv_bfloat16*& WH, const __nv_bfloat16*& WL, int& kb) {
        int pass = blk / KB;
        kb = (blk - pass * KB) * GBK;
        if (pass == 0) { AH = Ah1; AL = Al1; WH = Wh1; WL = Wl1; }
        else           { AH = Ah2; AL = Al2; WH = Wh2; WL = Wl2; }
    };

    int g = lane >> 3;
    int rA = (lane & 7) + ((g & 1) << 3);
    int kA = (g >> 1) << 3;
    int rB = (lane & 7) + ((g >> 1) << 3);
    int kB = (g & 1) << 3;

    {
        const __nv_bfloat16 *AH, *AL, *WH, *WL; int kb;
        pick(0, AH, AL, WH, WL, kb);
        load_block4(AH, AL, WH, WL, rbase, cbase, kb, K, Nr, M, sbase);
        asm volatile("cp.async.commit_group;");
    }

    for (int it = 0; it < total; it++) {
        if (it + 1 < total) {
            const __nv_bfloat16 *AH, *AL, *WH, *WL; int kb;
            pick(it + 1, AH, AL, WH, WL, kb);
            load_block4(AH, AL, WH, WL, rbase, cbase, kb, K, Nr, M,
                        sbase + ((it + 1) & 1) * BUF_B);
            asm volatile("cp.async.commit_group;");
            asm volatile("cp.async.wait_group 1;");
        } else {
            asm volatile("cp.async.wait_group 0;");
        }
        __syncthreads();

        uint32_t buf = sbase + (it & 1) * BUF_B;
        uint32_t bAh = buf;                     // Ah tile
        uint32_t bAl = buf + TILE_B;            // Al tile
        uint32_t bWh = buf + 2 * TILE_B;        // Wh tile
        uint32_t bWl = buf + 3 * TILE_B;        // Wl tile
#pragma unroll
        for (int s = 0; s < 2; s++) {
            // --- load Ah fragments (reused for terms 1 and 2) ---
            uint32_t ahf[4][4];
#pragma unroll
            for (int mt = 0; mt < 4; mt++) {
                uint32_t addr = bAh + (uint32_t)((wm + mt * 16 + rA) * ASTRIDE + s * 16 + kA) * 2;
                LDM_X4(ahf[mt][0], ahf[mt][1], ahf[mt][2], ahf[mt][3], addr);
            }
            // --- load Wh fragments (reused for terms 1 and 3) ---
            uint32_t bh[4][2];
#pragma unroll
            for (int np = 0; np < 2; np++) {
                uint32_t addr = bWh + (uint32_t)((wn + np * 16 + rB) * ASTRIDE + s * 16 + kB) * 2;
                uint32_t q0, q1, q2, q3;
                LDM_X4(q0, q1, q2, q3, addr);
                bh[np * 2][0] = q0; bh[np * 2][1] = q1;
                bh[np * 2 + 1][0] = q2; bh[np * 2 + 1][1] = q3;
            }
            // term 1: Ah * Wh
#pragma unroll
            for (int mt = 0; mt < 4; mt++)
#pragma unroll
                for (int nt = 0; nt < 4; nt++) MMA16816(acc[mt][nt], ahf[mt], bh[nt]);
            // --- load Wl fragments ---
            uint32_t bl[4][2];
#pragma unroll
            for (int np = 0; np < 2; np++) {
                uint32_t addr = bWl + (uint32_t)((wn + np * 16 + rB) * ASTRIDE + s * 16 + kB) * 2;
                uint32_t q0, q1, q2, q3;
                LDM_X4(q0, q1, q2, q3, addr);
                bl[np * 2][0] = q0; bl[np * 2][1] = q1;
                bl[np * 2 + 1][0] = q2; bl[np * 2 + 1][1] = q3;
            }
            // term 2: Ah * Wl (Ah fragments reused)
#pragma unroll
            for (int mt = 0; mt < 4; mt++)
#pragma unroll
                for (int nt = 0; nt < 4; nt++) MMA16816(acc[mt][nt], ahf[mt], bl[nt]);
            // --- load Al fragments ---
            uint32_t alf[4][4];
#pragma unroll
            for (int mt = 0; mt < 4; mt++) {
                uint32_t addr = bAl + (uint32_t)((wm + mt * 16 + rA) * ASTRIDE + s * 16 + kA) * 2;
                LDM_X4(alf[mt][0], alf[mt][1], alf[mt][2], alf[mt][3], addr);
            }
            // term 3: Al * Wh (Wh fragments reused)
#pragma unroll
            for (int mt = 0; mt < 4; mt++)
#pragma unroll
                for (int nt = 0; nt < 4; nt++) MMA16816(acc[mt][nt], alf[mt], bh[nt]);
        }
        __syncthreads();
    }

#pragma unroll
    for (int mt = 0; mt < 4; mt++) {
        int row0 = rbase + wm + mt * 16 + (lane >> 2);
        int row1 = row0 + 8;
#pragma unroll
        for (int nt = 0; nt < 4; nt++) {
            int col0 = cbase + wn + nt * 8 + (lane & 3) * 2;
            if (col0 < M) {
                float b0 = bias[col0];
                if (row0 < Nr) C[(size_t)row0 * M + col0] = acc[mt][nt][0] + b0;
                if (row1 < Nr) C[(size_t)row1 * M + col0] = acc[mt][nt][2] + b0;
            }
            if (col0 + 1 < M) {
                float b1 = bias[col0 + 1];
                if (row0 < Nr) C[(size_t)row0 * M + col0 + 1] = acc[mt][nt][1] + b1;
                if (row1 < Nr) C[(size_t)row1 * M + col0 + 1] = acc[mt][nt][3] + b1;
            }
        }
    }
}

// ---------------- GraphNorm ------------------------------------------------
#define GN_RB 64

__global__ void k_gn_stats(const float* __restrict__ h, const int* __restrict__ batch,
                           float* __restrict__ gsum, float* __restrict__ gsq) {
    int c = threadIdx.x;
    int r0 = blockIdx.x * GN_RB;
    int r1 = min(r0 + GN_RB, NN);
    int gcur = batch[r0];
    float s = 0.f, q = 0.f;
    for (int r = r0; r < r1; r++) {
        int g = batch[r];
        if (g != gcur) {
            atomicAdd(&gsum[gcur * HD + c], s);
            atomicAdd(&gsq[gcur * HD + c], q);
            s = 0.f; q = 0.f; gcur = g;
        }
        float v = h[(size_t)r * HD + c];
        s += v; q += v * v;
    }
    atomicAdd(&gsum[gcur * HD + c], s);
    atomicAdd(&gsq[gcur * HD + c], q);
}

__global__ void k_gn_coef(const float* __restrict__ gsum, const float* __restrict__ gsq,
                          const float* __restrict__ invsz,
                          const float* __restrict__ w, const float* __restrict__ b,
                          const float* __restrict__ a,
                          float* __restrict__ gS, float* __restrict__ gT) {
    int i = blockIdx.x * blockDim.x + threadIdx.x;
    if (i >= NG * HD) return;
    int g = i / HD, c = i - g * HD;
    float iv = invsz[g];
    float m = gsum[i] * iv;
    float e2 = gsq[i] * iv;
    float alc = a[c];
    float var = e2 - alc * (2.f - alc) * m * m;
    float S = rsqrtf(var + EPSV) * w[c];
    gS[i] = S;
    gT[i] = b[c] - alc * m * S;
}

__global__ void k_gn_apply2(const float* __restrict__ h, const int* __restrict__ batch,
                            const float* __restrict__ gS, const float* __restrict__ gT,
                            __nv_bfloat16* __restrict__ xh, __nv_bfloat16* __restrict__ xl) {
    int i4 = blockIdx.x * blockDim.x + threadIdx.x;
    const int n4 = NN * (HD / 4);
    if (i4 >= n4) return;
    int r = i4 >> 7;
    int c4 = (i4 & 127) * 4;
    int g = batch[r];
    float4 v = *((const float4*)h + i4);
    float4 S = *(const float4*)&gS[g * HD + c4];
    float4 T = *(const float4*)&gT[g * HD + c4];
    v.x = fmaxf(fmaf(v.x, S.x, T.x), 0.f);
    v.y = fmaxf(fmaf(v.y, S.y, T.y), 0.f);
    v.z = fmaxf(fmaf(v.z, S.z, T.z), 0.f);
    v.w = fmaxf(fmaf(v.w, S.w, T.w), 0.f);
    __nv_bfloat162 h01, h23, l01, l23;
    h01.x = __float2bfloat16_rn(v.x); h01.y = __float2bfloat16_rn(v.y);
    h23.x = __float2bfloat16_rn(v.z); h23.y = __float2bfloat16_rn(v.w);
    l01.x = __float2bfloat16_rn(v.x - __bfloat162float(h01.x));
    l01.y = __float2bfloat16_rn(v.y - __bfloat162float(h01.y));
    l23.x = __float2bfloat16_rn(v.z - __bfloat162float(h23.x));
    l23.y = __float2bfloat16_rn(v.w - __bfloat162float(h23.y));
    *(__nv_bfloat162*)(xh + (size_t)i4 * 4) = h01;
    *(__nv_bfloat162*)(xh + (size_t)i4 * 4 + 2) = h23;
    *(__nv_bfloat162*)(xl + (size_t)i4 * 4) = l01;
    *(__nv_bfloat162*)(xl + (size_t)i4 * 4 + 2) = l23;
}

// ---------------- host-side orchestration ----------------------------------
static float* symaddrf(const void* s) { void* p = nullptr; cudaGetSymbolAddress(&p, s); return (float*)p; }
static int* symaddri(const void* s) { void* p = nullptr; cudaGetSymbolAddress(&p, s); return (int*)p; }
static __nv_bfloat16* symaddrb(const void* s) { void* p = nullptr; cudaGetSymbolAddress(&p, s); return (__nv_bfloat16*)p; }

extern "C" void kernel_launch(void* const* d_in, const int* in_sizes, int n_in,
                              void* d_out, int out_size) {
    const float* x      = (const float*)d_in[0];
    const int*   ei     = (const int*)d_in[1];
    const int*   batch  = (const int*)d_in[2];
    const int*   src    = ei;
    const int*   dst    = ei + NE;

    const float* Wl[5] = {(const float*)d_in[3], (const float*)d_in[6], (const float*)d_in[9],
                          (const float*)d_in[12], (const float*)d_in[15]};
    const float* Wr[5] = {(const float*)d_in[4], (const float*)d_in[7], (const float*)d_in[10],
                          (const float*)d_in[13], (const float*)d_in[16]};
    const float* bb[5] = {(const float*)d_in[5], (const float*)d_in[8], (const float*)d_in[11],
                          (const float*)d_in[14], (const float*)d_in[17]};
    const float* gw[4] = {(const float*)d_in[18], (const float*)d_in[21], (const float*)d_in[24],
                          (const float*)d_in[27]};
    const float* gb[4] = {(const float*)d_in[19], (const float*)d_in[22], (const float*)d_in[25],
                          (const float*)d_in[28]};
    const float* ga[4] = {(const float*)d_in[20], (const float*)d_in[23], (const float*)d_in[26],
                          (const float*)d_in[29]};

    float* h1     = symaddrf(g_h1);
    int*   degi   = symaddri(g_degi);
    int*   rowptr = symaddri(g_rowptr);
    int*   cursor = symaddri(g_cursor);
    int*   csr    = symaddri(g_csr);
    float* invsz  = symaddrf(g_invsz);
    float* gsum   = symaddrf(g_gsum);
    float* gsq    = symaddrf(g_gsq);
    float* gS     = symaddrf(g_gS);
    float* gT     = symaddrf(g_gT);
    __nv_bfloat16* ah  = symaddrb(g_ah);
    __nv_bfloat16* al  = symaddrb(g_al);
    __nv_bfloat16* xh  = symaddrb(g_xh);
    __nv_bfloat16* xl  = symaddrb(g_xl);
    __nv_bfloat16* w1h = symaddrb(g_w1h);
    __nv_bfloat16* w1l = symaddrb(g_w1l);
    __nv_bfloat16* w2h = symaddrb(g_w2h);
    __nv_bfloat16* w2l = symaddrb(g_w2l);

    cudaFuncSetAttribute(k_gemm_tc, cudaFuncAttributeMaxDynamicSharedMemorySize, GEMM_DYN);

    auto Z = [&](void* p, size_t nfloats) {
        int n4 = (int)(nfloats / 4);
        int blocks = (n4 + 255) / 256;
        if (blocks > 32768) blocks = 32768;
        k_zero4<<<blocks, 256>>>((float4*)p, n4);
    };
    auto SPLIT = [&](const float* in, __nv_bfloat16* hi, __nv_bfloat16* lo,
                     int rows, int Kin, int Kpad) {
        int total = rows * Kpad;
        int blocks = (total + 255) / 256;
        if (blocks > 65535) blocks = 65535;
        k_split<<<blocks, 256>>>(in, hi, lo, rows, Kin, Kpad);
    };
    auto GEMM = [&](const float* bias, float* C, int Mout, int K) {
        dim3 grid((Mout + GBN - 1) / GBN, (NN + GBM - 1) / GBM);
        k_gemm_tc<<<grid, 256, GEMM_DYN>>>(ah, al, w1h, w1l, xh, xl, w2h, w2l,
                                           bias, C, NN, Mout, K);
    };

    // ---- CSR build + group sizes ----
    Z(degi, NN);
    Z(cursor, NN);
    k_count_i<<<(NE + 255) / 256, 256>>>(dst, degi, NE);
    k_scan2<<<1, 1024>>>(degi, rowptr);
    k_scatter<<<(NE + 255) / 256, 256>>>(src, dst, rowptr, cursor, csr);
    k_group_sizes<<<1, 32>>>(batch, invsz);

    auto gnorm = [&](float* h, const float* w, const float* bias, const float* alpha) {
        Z(gsum, (size_t)NG * HD);
        Z(gsq, (size_t)NG * HD);
        k_gn_stats<<<(NN + GN_RB - 1) / GN_RB, HD>>>(h, batch, gsum, gsq);
        k_gn_coef<<<(NG * HD + 255) / 256, 256>>>(gsum, gsq, invsz, w, bias, alpha, gS, gT);
        k_gn_apply2<<<(NN * (HD / 4) + 255) / 256, 256>>>(h, batch, gS, gT, xh, xl);
    };

    // ---- layer 1 (50 -> 512) ----
    k_aggcsr50<<<NN, 64>>>(x, rowptr, csr, ah, al);
    SPLIT(x, xh, xl, NN, FD, FDP);
    SPLIT(Wl[0], w1h, w1l, HD, FD, FDP);
    SPLIT(Wr[0], w2h, w2l, HD, FD, FDP);
    GEMM(bb[0], h1, HD, FDP);
    gnorm(h1, gw[0], gb[0], ga[0]);

    // ---- layers 2..4 (512 -> 512) ----
    for (int l = 1; l <= 3; l++) {
        k_aggcsr512<<<NN, 128>>>(xh, xl, rowptr, csr, ah, al);
        SPLIT(Wl[l], w1h, w1l, HD, HD, HD);
        SPLIT(Wr[l], w2h, w2l, HD, HD, HD);
        GEMM(bb[l], h1, HD, HD);
        gnorm(h1, gw[l], gb[l], ga[l]);
    }

    // ---- layer 5 (512 -> 121) -> d_out ----
    k_aggcsr512<<<NN, 128>>>(xh, xl, rowptr, csr, ah, al);
    SPLIT(Wl[4], w1h, w1l, OD, HD, HD);
    SPLIT(Wr[4], w2h, w2l, OD, HD, HD);
    GEMM(bb[4], (float*)d_out, OD, HD);
}